// round 1
// baseline (speedup 1.0000x reference)
#include <cuda_runtime.h>
#include <cuda_bf16.h>
#include <math_constants.h>

#define TT 2048
#define HH 2048
#define NHEAD 16
#define HD 128
#define D2 256

// ---------------- scratch (static device globals; no allocation) ----------------
__device__ float g_qr[TT*HH];   // quantized real activations (reused for attn-out quant)
__device__ float g_qi[TT*HH];
__device__ float g_pqr[TT*HH];  // q projection real
__device__ float g_pqi[TT*HH];
__device__ float g_pkr[TT*HH];
__device__ float g_pki[TT*HH];
__device__ float g_pvr[TT*HH];
__device__ float g_pvi[TT*HH];
__device__ float g_ar[TT*HH];   // attention output real
__device__ float g_ai[TT*HH];
__device__ float g_cos[TT*HD];
__device__ float g_sin[TT*HD];

// ---------------- per-row symmetric int8 fake-quant ----------------
// matches: scale = 127/max(max|x|,1e-5); q = clip(round(x*scale),-128,127)/scale
// jnp.round = round-half-to-even = rintf
__global__ void rowquant_kernel(const float* __restrict__ x, float* __restrict__ q) {
    __shared__ float red[256];
    int row = blockIdx.x;
    const float* xr = x + row * HH;
    float m = 0.f;
    for (int c = threadIdx.x; c < HH; c += 256) m = fmaxf(m, fabsf(xr[c]));
    red[threadIdx.x] = m;
    __syncthreads();
    for (int s = 128; s > 0; s >>= 1) {
        if (threadIdx.x < s) red[threadIdx.x] = fmaxf(red[threadIdx.x], red[threadIdx.x + s]);
        __syncthreads();
    }
    float scale = 127.0f / fmaxf(red[0], 1e-5f);
    for (int c = threadIdx.x; c < HH; c += 256) {
        float v = rintf(xr[c] * scale);
        v = fminf(fmaxf(v, -128.f), 127.f);
        q[row * HH + c] = v / scale;
    }
}

// ---------------- cos/sin cache, rounded through bf16 like the reference ----------------
__global__ void cossin_kernel(const int* __restrict__ pos) {
    int idx = blockIdx.x * 256 + threadIdx.x;
    if (idx >= TT * HD) return;
    int t = idx / HD, d = idx % HD;
    float invf = 1.0f / powf(10000.0f, (float)d / (float)HD);
    float f = (float)pos[t] * invf;
    g_cos[idx] = __bfloat162float(__float2bfloat16(cosf(f)));
    g_sin[idx] = __bfloat162float(__float2bfloat16(sinf(f)));
}

// ---------------- complex RoPE (in place) ----------------
__global__ void rope_kernel(float* __restrict__ xr, float* __restrict__ xi) {
    int idx = blockIdx.x * 256 + threadIdx.x;  // over T*H
    int t = idx >> 11;          // / HH
    int d = idx & (HD - 1);     // (idx % HH) % HD
    float c = g_cos[t * HD + d];
    float s = g_sin[t * HD + d];
    float r = xr[idx], im = xi[idx];
    xr[idx] = r * c - im * s;
    xi[idx] = im * c + r * s;
}

// ---------------- dual GEMM: C = A1 @ B1^T + sign * (A2 @ B2^T) ----------------
// All matrices [2048, 2048] row-major; B accessed as [N,K] (K contiguous).
// Classic 128x128x8 tile, 256 threads, 8x8 register tile per thread.
__global__ __launch_bounds__(256) void gemm_dual_kernel(
    const float* __restrict__ A1, const float* __restrict__ B1,
    const float* __restrict__ A2, const float* __restrict__ B2,
    float sign, float* __restrict__ C) {
    __shared__ __align__(16) float As[8][128];
    __shared__ __align__(16) float Bs[8][128];
    int tid = threadIdx.x;
    int tx = tid & 15, ty = tid >> 4;
    int m0 = blockIdx.y * 128, n0 = blockIdx.x * 128;
    int lrow = tid >> 1;
    int lcol = (tid & 1) * 4;

    float acc[8][8];
#pragma unroll
    for (int i = 0; i < 8; i++)
#pragma unroll
        for (int j = 0; j < 8; j++) acc[i][j] = 0.f;

    for (int seg = 0; seg < 2; ++seg) {
        const float* A = seg ? A2 : A1;
        const float* B = seg ? B2 : B1;
        float sg = seg ? sign : 1.0f;
        const float* aptr = A + (m0 + lrow) * HH + lcol;
        const float* bptr = B + (n0 + lrow) * HH + lcol;
        for (int k0 = 0; k0 < HH; k0 += 8) {
            float4 av = *(const float4*)(aptr + k0);
            float4 bv = *(const float4*)(bptr + k0);
            __syncthreads();
            As[lcol + 0][lrow] = av.x; As[lcol + 1][lrow] = av.y;
            As[lcol + 2][lrow] = av.z; As[lcol + 3][lrow] = av.w;
            Bs[lcol + 0][lrow] = bv.x * sg; Bs[lcol + 1][lrow] = bv.y * sg;
            Bs[lcol + 2][lrow] = bv.z * sg; Bs[lcol + 3][lrow] = bv.w * sg;
            __syncthreads();
#pragma unroll
            for (int k = 0; k < 8; ++k) {
                float4 a0 = *(const float4*)&As[k][ty * 8];
                float4 a1 = *(const float4*)&As[k][ty * 8 + 4];
                float4 b0 = *(const float4*)&Bs[k][tx * 8];
                float4 b1 = *(const float4*)&Bs[k][tx * 8 + 4];
                float ar[8] = {a0.x, a0.y, a0.z, a0.w, a1.x, a1.y, a1.z, a1.w};
                float br[8] = {b0.x, b0.y, b0.z, b0.w, b1.x, b1.y, b1.z, b1.w};
#pragma unroll
                for (int i = 0; i < 8; i++)
#pragma unroll
                    for (int j = 0; j < 8; j++)
                        acc[i][j] = fmaf(ar[i], br[j], acc[i][j]);
            }
        }
    }
#pragma unroll
    for (int i = 0; i < 8; i++) {
        int row = m0 + ty * 8 + i;
        float4* cp = (float4*)(C + row * HH + n0 + tx * 8);
        cp[0] = make_float4(acc[i][0], acc[i][1], acc[i][2], acc[i][3]);
        cp[1] = make_float4(acc[i][4], acc[i][5], acc[i][6], acc[i][7]);
    }
}

// ---------------- causal flash attention, head_dim = 256 (= [real | imag]) ----------------
#define QPAD 68
#define PSLD 68
__global__ __launch_bounds__(256) void flash_kernel(
    const float* __restrict__ qr, const float* __restrict__ qi,
    const float* __restrict__ kr, const float* __restrict__ ki,
    const float* __restrict__ vr, const float* __restrict__ vi,
    float* __restrict__ outr, float* __restrict__ outi) {
    extern __shared__ float sm[];
    float* Qst = sm;                       // [256][QPAD] (d-major, transposed)
    float* Kst = Qst + D2 * QPAD;          // [256][QPAD]
    float* Vs  = Kst + D2 * QPAD;          // [64][256]
    float* Ps  = Vs + 64 * D2;             // [64][PSLD]

    int head = blockIdx.y;
    int qb = (int)gridDim.x - 1 - (int)blockIdx.x;  // heavy blocks first
    int tid = threadIdx.x;
    int tx = tid & 15, ty = tid >> 4;
    int hoff = head * HD;

    // load Q tile (64 rows x 256 dims), transposed into smem
    for (int e = tid; e < 64 * D2; e += 256) {
        int m = e >> 8, dd = e & 255;
        int t = qb * 64 + m;
        float v = (dd < HD) ? qr[t * HH + hoff + dd] : qi[t * HH + hoff + dd - HD];
        Qst[dd * QPAD + m] = v;
    }

    float mrow[4], lsum[4], accO[4][16];
#pragma unroll
    for (int i = 0; i < 4; i++) {
        mrow[i] = -CUDART_INF_F;
        lsum[i] = 0.f;
#pragma unroll
        for (int j = 0; j < 16; j++) accO[i][j] = 0.f;
    }

    for (int kb = 0; kb <= qb; ++kb) {
        __syncthreads();  // previous PV done (and Q load covered on first iter)
        for (int e = tid; e < 64 * D2; e += 256) {
            int n = e >> 8, dd = e & 255;
            int s = kb * 64 + n;
            float kv = (dd < HD) ? kr[s * HH + hoff + dd] : ki[s * HH + hoff + dd - HD];
            Kst[dd * QPAD + n] = kv;
            float vv = (dd < HD) ? vr[s * HH + hoff + dd] : vi[s * HH + hoff + dd - HD];
            Vs[n * D2 + dd] = vv;
        }
        __syncthreads();

        // S = Q K^T (4x4 per thread over 256 dims)
        float S[4][4];
#pragma unroll
        for (int i = 0; i < 4; i++)
#pragma unroll
            for (int j = 0; j < 4; j++) S[i][j] = 0.f;
#pragma unroll 4
        for (int kk = 0; kk < D2; ++kk) {
            float4 a = *(const float4*)&Qst[kk * QPAD + ty * 4];
            float4 b = *(const float4*)&Kst[kk * QPAD + tx * 4];
            float aa[4] = {a.x, a.y, a.z, a.w};
            float bb[4] = {b.x, b.y, b.z, b.w};
#pragma unroll
            for (int i = 0; i < 4; i++)
#pragma unroll
                for (int j = 0; j < 4; j++)
                    S[i][j] = fmaf(aa[i], bb[j], S[i][j]);
        }

        // scale + causal mask + online softmax
        int rbase = qb * 64 + ty * 4;
        int cbase = kb * 64 + tx * 4;
        float mloc[4];
#pragma unroll
        for (int i = 0; i < 4; i++) {
            mloc[i] = -CUDART_INF_F;
#pragma unroll
            for (int j = 0; j < 4; j++) {
                float sv = S[i][j] * 0.0625f;  // 1/sqrt(2*D)
                if (cbase + j > rbase + i) sv = -1e9f;
                S[i][j] = sv;
                mloc[i] = fmaxf(mloc[i], sv);
            }
        }
#pragma unroll
        for (int i = 0; i < 4; i++)
            for (int off = 8; off; off >>= 1)
                mloc[i] = fmaxf(mloc[i], __shfl_xor_sync(0xffffffffu, mloc[i], off));

#pragma unroll
        for (int i = 0; i < 4; i++) {
            float mnew = fmaxf(mrow[i], mloc[i]);
            float f = expf(mrow[i] - mnew);
            float rsum = 0.f;
#pragma unroll
            for (int j = 0; j < 4; j++) {
                float p = expf(S[i][j] - mnew);
                S[i][j] = p;
                rsum += p;
            }
            for (int off = 8; off; off >>= 1)
                rsum += __shfl_xor_sync(0xffffffffu, rsum, off);
            lsum[i] = lsum[i] * f + rsum;
            mrow[i] = mnew;
#pragma unroll
            for (int j = 0; j < 16; j++) accO[i][j] *= f;
#pragma unroll
            for (int j = 0; j < 4; j++)
                Ps[(ty * 4 + i) * PSLD + tx * 4 + j] = S[i][j];
        }
        __syncthreads();

        // O += P @ V (4 rows x 16 cols per thread)
#pragma unroll 2
        for (int n = 0; n < 64; ++n) {
            float pv[4];
#pragma unroll
            for (int i = 0; i < 4; i++) pv[i] = Ps[(ty * 4 + i) * PSLD + n];
            const float* vrow = &Vs[n * D2 + tx * 16];
            float4 v0 = *(const float4*)(vrow);
            float4 v1 = *(const float4*)(vrow + 4);
            float4 v2 = *(const float4*)(vrow + 8);
            float4 v3 = *(const float4*)(vrow + 12);
            float vv[16] = {v0.x, v0.y, v0.z, v0.w, v1.x, v1.y, v1.z, v1.w,
                            v2.x, v2.y, v2.z, v2.w, v3.x, v3.y, v3.z, v3.w};
#pragma unroll
            for (int i = 0; i < 4; i++)
#pragma unroll
                for (int j = 0; j < 16; j++)
                    accO[i][j] = fmaf(pv[i], vv[j], accO[i][j]);
        }
    }

    // epilogue: normalize and scatter to [T, H] real/imag
#pragma unroll
    for (int i = 0; i < 4; i++) {
        int t = qb * 64 + ty * 4 + i;
        float invl = 1.0f / lsum[i];
#pragma unroll
        for (int j = 0; j < 16; j++) {
            int c = tx * 16 + j;
            float val = accO[i][j] * invl;
            if (c < HD) outr[t * HH + hoff + c] = val;
            else        outi[t * HH + hoff + c - HD] = val;
        }
    }
}

// ---------------- launch ----------------
extern "C" void kernel_launch(void* const* d_in, const int* in_sizes, int n_in,
                              void* d_out, int out_size) {
    const float* hr   = (const float*)d_in[0];
    const float* hi   = (const float*)d_in[1];
    const int*   pos  = (const int*)d_in[2];
    const float* Wq_r = (const float*)d_in[3];
    const float* Wq_i = (const float*)d_in[4];
    const float* Wk_r = (const float*)d_in[5];
    const float* Wk_i = (const float*)d_in[6];
    const float* Wv_r = (const float*)d_in[7];
    const float* Wv_i = (const float*)d_in[8];
    const float* Wo_r = (const float*)d_in[9];
    const float* Wo_i = (const float*)d_in[10];
    float* out = (float*)d_out;

    float *qr, *qi, *pqr, *pqi, *pkr, *pki, *pvr, *pvi, *ar, *ai;
    cudaGetSymbolAddress((void**)&qr,  g_qr);
    cudaGetSymbolAddress((void**)&qi,  g_qi);
    cudaGetSymbolAddress((void**)&pqr, g_pqr);
    cudaGetSymbolAddress((void**)&pqi, g_pqi);
    cudaGetSymbolAddress((void**)&pkr, g_pkr);
    cudaGetSymbolAddress((void**)&pki, g_pki);
    cudaGetSymbolAddress((void**)&pvr, g_pvr);
    cudaGetSymbolAddress((void**)&pvi, g_pvi);
    cudaGetSymbolAddress((void**)&ar,  g_ar);
    cudaGetSymbolAddress((void**)&ai,  g_ai);

    // quantize hidden once (shared by Q/K/V projections)
    rowquant_kernel<<<TT, 256>>>(hr, qr);
    rowquant_kernel<<<TT, 256>>>(hi, qi);
    cossin_kernel<<<(TT * HD) / 256, 256>>>(pos);

    dim3 gg(HH / 128, TT / 128);
    // yr = qr@Wr^T + qi@Wi^T ; yi = qr@Wi^T - qi@Wr^T
    gemm_dual_kernel<<<gg, 256>>>(qr, Wq_r, qi, Wq_i,  1.f, pqr);
    gemm_dual_kernel<<<gg, 256>>>(qr, Wq_i, qi, Wq_r, -1.f, pqi);
    gemm_dual_kernel<<<gg, 256>>>(qr, Wk_r, qi, Wk_i,  1.f, pkr);
    gemm_dual_kernel<<<gg, 256>>>(qr, Wk_i, qi, Wk_r, -1.f, pki);
    gemm_dual_kernel<<<gg, 256>>>(qr, Wv_r, qi, Wv_i,  1.f, pvr);
    gemm_dual_kernel<<<gg, 256>>>(qr, Wv_i, qi, Wv_r, -1.f, pvi);

    rope_kernel<<<(TT * HH) / 256, 256>>>(pqr, pqi);
    rope_kernel<<<(TT * HH) / 256, 256>>>(pkr, pki);

    const int FLASH_SMEM = (D2 * QPAD * 2 + 64 * D2 + 64 * PSLD) * 4;  // 222208 B
    cudaFuncSetAttribute(flash_kernel, cudaFuncAttributeMaxDynamicSharedMemorySize, FLASH_SMEM);
    flash_kernel<<<dim3(TT / 64, NHEAD), 256, FLASH_SMEM>>>(pqr, pqi, pkr, pki, pvr, pvi, ar, ai);

    // output projection (quantized attention outputs), tuple (yr, yi) -> [2, T, H]
    rowquant_kernel<<<TT, 256>>>(ar, qr);
    rowquant_kernel<<<TT, 256>>>(ai, qi);
    gemm_dual_kernel<<<gg, 256>>>(qr, Wo_r, qi, Wo_i,  1.f, out);
    gemm_dual_kernel<<<gg, 256>>>(qr, Wo_i, qi, Wo_r, -1.f, out + TT * HH);
}

// round 3
// speedup vs baseline: 2.2581x; 2.2581x over previous
#include <cuda_runtime.h>
#include <cuda_bf16.h>
#include <math_constants.h>
#include <cstdint>

#define TT 2048
#define HH 2048
#define NHEAD 16
#define HD 128
#define D2 256

// ======================= scratch (static device globals) =======================
__device__ __nv_bfloat16 g_nr[TT*HH];      // quantized int-valued activations (bf16, exact)
__device__ __nv_bfloat16 g_ni[TT*HH];
__device__ float g_invs1[TT];
__device__ float g_invs2[TT];
__device__ float g_invs3[TT];
__device__ float g_invs4[TT];
__device__ __nv_bfloat16 g_wsp[16][HH*HH]; // weight hi/lo splits: [2*w+0]=hi, [2*w+1]=lo
__device__ float g_pqr[TT*HH];
__device__ float g_pqi[TT*HH];
__device__ float g_pkr[TT*HH];
__device__ float g_pki[TT*HH];
__device__ float g_pvr[TT*HH];
__device__ float g_pvi[TT*HH];
__device__ float g_ar[TT*HH];
__device__ float g_ai[TT*HH];
__device__ float g_cos[TT*HD];
__device__ float g_sin[TT*HD];

// ======================= helpers =======================
__device__ __forceinline__ uint32_t smem_u32(const void* p) {
    uint32_t a;
    asm("{ .reg .u64 t; cvta.to.shared.u64 t, %1; cvt.u32.u64 %0, t; }" : "=r"(a) : "l"(p));
    return a;
}
#define SWZ128(b) ((b) ^ (((b) >> 3) & 0x70))

// ======================= prep kernels =======================
__global__ void rowquant_bf16_kernel(const float* __restrict__ x,
                                     __nv_bfloat16* __restrict__ q,
                                     float* __restrict__ invs) {
    __shared__ float red[256];
    int row = blockIdx.x;
    const float* xr = x + row * HH;
    float m = 0.f;
    for (int c = threadIdx.x; c < HH; c += 256) m = fmaxf(m, fabsf(xr[c]));
    red[threadIdx.x] = m;
    __syncthreads();
    for (int s = 128; s > 0; s >>= 1) {
        if (threadIdx.x < s) red[threadIdx.x] = fmaxf(red[threadIdx.x], red[threadIdx.x + s]);
        __syncthreads();
    }
    float scale = 127.0f / fmaxf(red[0], 1e-5f);
    if (threadIdx.x == 0) invs[row] = 1.0f / scale;
    for (int c = threadIdx.x; c < HH; c += 256) {
        float v = rintf(xr[c] * scale);
        v = fminf(fmaxf(v, -128.f), 127.f);
        q[row * HH + c] = __float2bfloat16_rn(v);
    }
}

__global__ void split_kernel(const float* __restrict__ w,
                             __nv_bfloat16* __restrict__ hi,
                             __nv_bfloat16* __restrict__ lo) {
    int i = (blockIdx.x * 256 + threadIdx.x) * 4;
    float4 v = *(const float4*)(w + i);
    __nv_bfloat16 h[4], l[4];
    float vv[4] = {v.x, v.y, v.z, v.w};
#pragma unroll
    for (int j = 0; j < 4; j++) {
        h[j] = __float2bfloat16_rn(vv[j]);
        l[j] = __float2bfloat16_rn(vv[j] - __bfloat162float(h[j]));
    }
    *(uint64_t*)(hi + i) = *(uint64_t*)h;
    *(uint64_t*)(lo + i) = *(uint64_t*)l;
}

__global__ void cossin_kernel(const int* __restrict__ pos) {
    int idx = blockIdx.x * 256 + threadIdx.x;
    if (idx >= TT * HD) return;
    int t = idx / HD, d = idx % HD;
    float invf = 1.0f / powf(10000.0f, (float)d / (float)HD);
    float f = (float)pos[t] * invf;
    g_cos[idx] = __bfloat162float(__float2bfloat16(cosf(f)));
    g_sin[idx] = __bfloat162float(__float2bfloat16(sinf(f)));
}

__global__ void rope_kernel(float* __restrict__ xr, float* __restrict__ xi) {
    int idx = blockIdx.x * 256 + threadIdx.x;
    int t = idx >> 11;
    int d = idx & (HD - 1);
    float c = g_cos[t * HD + d];
    float s = g_sin[t * HD + d];
    float r = xr[idx], im = xi[idx];
    xr[idx] = r * c - im * s;
    xi[idx] = im * c + r * s;
}

// ======================= mma.sync dual GEMM =======================
// C[m0:128, n0:128] = invs1[m]*(A1 @ (B1hi+B1lo)^T) + sign*invs2[m]*(A2 @ (B2hi+B2lo)^T)
// smem tiles: A 128x64 bf16 (128B rows, SW128), B 128x64 bf16. 4-stage cp.async ring.
#define STAGES 4
#define NCHUNK 128          // 4 passes x 32 k-chunks of 64
#define STG_SZ 32768        // 16KB A + 16KB B

__device__ __forceinline__ void load_chunk(uint32_t sa, uint32_t sb,
                                           const __nv_bfloat16* Aseg,
                                           const __nv_bfloat16* Bseg,
                                           int m0, int n0, int kc, int tid) {
    const char* ag = (const char*)(Aseg + (size_t)m0 * HH + kc * 64);
    const char* bg = (const char*)(Bseg + (size_t)n0 * HH + kc * 64);
#pragma unroll
    for (int i = 0; i < 4; i++) {   // A: 128 rows x 8 x 16B
        int idx = tid + i * 256;
        int r = idx >> 3, g = idx & 7;
        uint32_t so = sa + SWZ128(r * 128 + g * 16);
        asm volatile("cp.async.cg.shared.global [%0], [%1], 16;"
                     :: "r"(so), "l"(ag + (size_t)r * 4096 + g * 16));
    }
#pragma unroll
    for (int i = 0; i < 4; i++) {   // B: 128 rows x 8 x 16B
        int idx = tid + i * 256;
        int r = idx >> 3, g = idx & 7;
        uint32_t so = sb + SWZ128(r * 128 + g * 16);
        asm volatile("cp.async.cg.shared.global [%0], [%1], 16;"
                     :: "r"(so), "l"(bg + (size_t)r * 4096 + g * 16));
    }
}

// compute one K=64 chunk: warp tile 64x32, 16x m16n8k16 per k-step, 4 k-steps
__device__ __forceinline__ void compute_chunk(uint32_t sa, uint32_t sb,
                                              int warp_m, int warp_n, int lane,
                                              float (&acc)[4][4][4]) {
#pragma unroll
    for (int ks = 0; ks < 4; ks++) {
        uint32_t af[4][4];
#pragma unroll
        for (int mi = 0; mi < 4; mi++) {
            int r = warp_m * 64 + mi * 16 + (lane & 15);
            int cb = ks * 32 + (lane >> 4) * 16;
            uint32_t ad = sa + SWZ128(r * 128 + cb);
            asm volatile("ldmatrix.sync.aligned.m8n8.x4.shared.b16 {%0,%1,%2,%3}, [%4];"
                : "=r"(af[mi][0]), "=r"(af[mi][1]), "=r"(af[mi][2]), "=r"(af[mi][3])
                : "r"(ad));
        }
        uint32_t bf[4][2];
#pragma unroll
        for (int p = 0; p < 2; p++) {
            int nr = warp_n * 32 + p * 16 + (lane & 7) + ((lane >> 4) << 3);
            int cb = ks * 32 + ((lane >> 3) & 1) * 16;
            uint32_t bd = sb + SWZ128(nr * 128 + cb);
            asm volatile("ldmatrix.sync.aligned.m8n8.x4.shared.b16 {%0,%1,%2,%3}, [%4];"
                : "=r"(bf[2*p][0]), "=r"(bf[2*p][1]), "=r"(bf[2*p+1][0]), "=r"(bf[2*p+1][1])
                : "r"(bd));
        }
#pragma unroll
        for (int mi = 0; mi < 4; mi++)
#pragma unroll
            for (int nj = 0; nj < 4; nj++)
                asm volatile(
                    "mma.sync.aligned.m16n8k16.row.col.f32.bf16.bf16.f32 "
                    "{%0,%1,%2,%3}, {%4,%5,%6,%7}, {%8,%9}, {%0,%1,%2,%3};"
                    : "+f"(acc[mi][nj][0]), "+f"(acc[mi][nj][1]),
                      "+f"(acc[mi][nj][2]), "+f"(acc[mi][nj][3])
                    : "r"(af[mi][0]), "r"(af[mi][1]), "r"(af[mi][2]), "r"(af[mi][3]),
                      "r"(bf[nj][0]), "r"(bf[nj][1]));
    }
}

__global__ __launch_bounds__(256, 1) void gemm_dual_mma(
    const __nv_bfloat16* __restrict__ A1, const __nv_bfloat16* __restrict__ A2,
    const __nv_bfloat16* __restrict__ B1hi, const __nv_bfloat16* __restrict__ B1lo,
    const __nv_bfloat16* __restrict__ B2hi, const __nv_bfloat16* __restrict__ B2lo,
    const float* __restrict__ invs1, const float* __restrict__ invs2,
    float sign, float* __restrict__ C) {
    extern __shared__ char smem[];
    uint32_t sbase = smem_u32(smem);
    int tid = threadIdx.x;
    int wid = tid >> 5, lane = tid & 31;
    int warp_m = wid >> 2, warp_n = wid & 3;
    int m0 = blockIdx.y * 128, n0 = blockIdx.x * 128;

    float acc1[4][4][4], acc2[4][4][4];
#pragma unroll
    for (int a = 0; a < 4; a++)
#pragma unroll
        for (int b = 0; b < 4; b++)
#pragma unroll
            for (int c = 0; c < 4; c++) { acc1[a][b][c] = 0.f; acc2[a][b][c] = 0.f; }

    // prologue: chunks 0..3 (pass 0: A1 / B1hi)
    for (int c = 0; c < STAGES; c++) {
        uint32_t st = sbase + c * STG_SZ;
        load_chunk(st, st + 16384, A1, B1hi, m0, n0, c, tid);
        asm volatile("cp.async.commit_group;");
    }

    for (int c = 0; c < NCHUNK; c++) {
        int stage = c & (STAGES - 1);
        uint32_t st = sbase + stage * STG_SZ;
        int rem = NCHUNK - 1 - c;
        if (rem >= 3)      asm volatile("cp.async.wait_group 3;");
        else if (rem == 2) asm volatile("cp.async.wait_group 2;");
        else if (rem == 1) asm volatile("cp.async.wait_group 1;");
        else               asm volatile("cp.async.wait_group 0;");
        __syncthreads();

        if (c < 64) compute_chunk(st, st + 16384, warp_m, warp_n, lane, acc1);
        else        compute_chunk(st, st + 16384, warp_m, warp_n, lane, acc2);
        __syncthreads();

        int cn = c + STAGES;
        if (cn < NCHUNK) {
            int sel = cn >> 5;
            const __nv_bfloat16* Bseg = (sel == 0) ? B1hi : (sel == 1) ? B1lo
                                       : (sel == 2) ? B2hi : B2lo;
            const __nv_bfloat16* Aseg = (cn >= 64) ? A2 : A1;
            load_chunk(st, st + 16384, Aseg, Bseg, m0, n0, cn & 31, tid);
            asm volatile("cp.async.commit_group;");
        }
    }

    // epilogue: C = invs1[row]*acc1 + sign*invs2[row]*acc2
    int tq = lane >> 2, tr = lane & 3;
#pragma unroll
    for (int mi = 0; mi < 4; mi++) {
#pragma unroll
        for (int h = 0; h < 2; h++) {
            int row = m0 + warp_m * 64 + mi * 16 + tq + h * 8;
            float a = invs1[row];
            float b = sign * invs2[row];
            float* crow = C + (size_t)row * HH + n0 + warp_n * 32;
#pragma unroll
            for (int nj = 0; nj < 4; nj++) {
                float2 o;
                o.x = a * acc1[mi][nj][2*h]     + b * acc2[mi][nj][2*h];
                o.y = a * acc1[mi][nj][2*h + 1] + b * acc2[mi][nj][2*h + 1];
                *(float2*)(crow + nj * 8 + 2 * tr) = o;
            }
        }
    }
}

// ======================= causal flash attention (fp32, head_dim 256) =======================
#define QPAD 68
#define PSLD 68
__global__ __launch_bounds__(256) void flash_kernel(
    const float* __restrict__ qr, const float* __restrict__ qi,
    const float* __restrict__ kr, const float* __restrict__ ki,
    const float* __restrict__ vr, const float* __restrict__ vi,
    float* __restrict__ outr, float* __restrict__ outi) {
    extern __shared__ float sm[];
    float* Qst = sm;
    float* Kst = Qst + D2 * QPAD;
    float* Vs  = Kst + D2 * QPAD;
    float* Ps  = Vs + 64 * D2;

    int head = blockIdx.y;
    int qb = (int)gridDim.x - 1 - (int)blockIdx.x;
    int tid = threadIdx.x;
    int tx = tid & 15, ty = tid >> 4;
    int hoff = head * HD;

    for (int e = tid; e < 64 * D2; e += 256) {
        int m = e >> 8, dd = e & 255;
        int t = qb * 64 + m;
        float v = (dd < HD) ? qr[t * HH + hoff + dd] : qi[t * HH + hoff + dd - HD];
        Qst[dd * QPAD + m] = v;
    }

    float mrow[4], lsum[4], accO[4][16];
#pragma unroll
    for (int i = 0; i < 4; i++) {
        mrow[i] = -CUDART_INF_F;
        lsum[i] = 0.f;
#pragma unroll
        for (int j = 0; j < 16; j++) accO[i][j] = 0.f;
    }

    for (int kb = 0; kb <= qb; ++kb) {
        __syncthreads();
        for (int e = tid; e < 64 * D2; e += 256) {
            int n = e >> 8, dd = e & 255;
            int s = kb * 64 + n;
            float kv = (dd < HD) ? kr[s * HH + hoff + dd] : ki[s * HH + hoff + dd - HD];
            Kst[dd * QPAD + n] = kv;
            float vv = (dd < HD) ? vr[s * HH + hoff + dd] : vi[s * HH + hoff + dd - HD];
            Vs[n * D2 + dd] = vv;
        }
        __syncthreads();

        float S[4][4];
#pragma unroll
        for (int i = 0; i < 4; i++)
#pragma unroll
            for (int j = 0; j < 4; j++) S[i][j] = 0.f;
#pragma unroll 4
        for (int kk = 0; kk < D2; ++kk) {
            float4 aq = *(const float4*)&Qst[kk * QPAD + ty * 4];
            float4 bq = *(const float4*)&Kst[kk * QPAD + tx * 4];
            float aa[4] = {aq.x, aq.y, aq.z, aq.w};
            float bb[4] = {bq.x, bq.y, bq.z, bq.w};
#pragma unroll
            for (int i = 0; i < 4; i++)
#pragma unroll
                for (int j = 0; j < 4; j++)
                    S[i][j] = fmaf(aa[i], bb[j], S[i][j]);
        }

        int rbase = qb * 64 + ty * 4;
        int cbase = kb * 64 + tx * 4;
        float mloc[4];
#pragma unroll
        for (int i = 0; i < 4; i++) {
            mloc[i] = -CUDART_INF_F;
#pragma unroll
            for (int j = 0; j < 4; j++) {
                float sv = S[i][j] * 0.0625f;
                if (cbase + j > rbase + i) sv = -1e9f;
                S[i][j] = sv;
                mloc[i] = fmaxf(mloc[i], sv);
            }
        }
#pragma unroll
        for (int i = 0; i < 4; i++)
            for (int off = 8; off; off >>= 1)
                mloc[i] = fmaxf(mloc[i], __shfl_xor_sync(0xffffffffu, mloc[i], off));

#pragma unroll
        for (int i = 0; i < 4; i++) {
            float mnew = fmaxf(mrow[i], mloc[i]);
            float f = expf(mrow[i] - mnew);
            float rsum = 0.f;
#pragma unroll
            for (int j = 0; j < 4; j++) {
                float p = expf(S[i][j] - mnew);
                S[i][j] = p;
                rsum += p;
            }
            for (int off = 8; off; off >>= 1)
                rsum += __shfl_xor_sync(0xffffffffu, rsum, off);
            lsum[i] = lsum[i] * f + rsum;
            mrow[i] = mnew;
#pragma unroll
            for (int j = 0; j < 16; j++) accO[i][j] *= f;
#pragma unroll
            for (int j = 0; j < 4; j++)
                Ps[(ty * 4 + i) * PSLD + tx * 4 + j] = S[i][j];
        }
        __syncthreads();

#pragma unroll 2
        for (int n = 0; n < 64; ++n) {
            float pv[4];
#pragma unroll
            for (int i = 0; i < 4; i++) pv[i] = Ps[(ty * 4 + i) * PSLD + n];
            const float* vrow = &Vs[n * D2 + tx * 16];
            float4 v0 = *(const float4*)(vrow);
            float4 v1 = *(const float4*)(vrow + 4);
            float4 v2 = *(const float4*)(vrow + 8);
            float4 v3 = *(const float4*)(vrow + 12);
            float vv[16] = {v0.x, v0.y, v0.z, v0.w, v1.x, v1.y, v1.z, v1.w,
                            v2.x, v2.y, v2.z, v2.w, v3.x, v3.y, v3.z, v3.w};
#pragma unroll
            for (int i = 0; i < 4; i++)
#pragma unroll
                for (int j = 0; j < 16; j++)
                    accO[i][j] = fmaf(pv[i], vv[j], accO[i][j]);
        }
    }

#pragma unroll
    for (int i = 0; i < 4; i++) {
        int t = qb * 64 + ty * 4 + i;
        float invl = 1.0f / lsum[i];
#pragma unroll
        for (int j = 0; j < 16; j++) {
            int c = tx * 16 + j;
            float val = accO[i][j] * invl;
            if (c < HD) outr[t * HH + hoff + c] = val;
            else        outi[t * HH + hoff + c - HD] = val;
        }
    }
}

// ======================= launch =======================
extern "C" void kernel_launch(void* const* d_in, const int* in_sizes, int n_in,
                              void* d_out, int out_size) {
    const float* hr   = (const float*)d_in[0];
    const float* hi   = (const float*)d_in[1];
    const int*   pos  = (const int*)d_in[2];
    const float* W[8] = {(const float*)d_in[3], (const float*)d_in[4],
                         (const float*)d_in[5], (const float*)d_in[6],
                         (const float*)d_in[7], (const float*)d_in[8],
                         (const float*)d_in[9], (const float*)d_in[10]};
    float* out = (float*)d_out;

    __nv_bfloat16 *nr, *ni, *wsp;
    float *is1, *is2, *is3, *is4, *pqr, *pqi, *pkr, *pki, *pvr, *pvi, *ar, *ai;
    cudaGetSymbolAddress((void**)&nr,  g_nr);
    cudaGetSymbolAddress((void**)&ni,  g_ni);
    cudaGetSymbolAddress((void**)&is1, g_invs1);
    cudaGetSymbolAddress((void**)&is2, g_invs2);
    cudaGetSymbolAddress((void**)&is3, g_invs3);
    cudaGetSymbolAddress((void**)&is4, g_invs4);
    cudaGetSymbolAddress((void**)&wsp, g_wsp);
    cudaGetSymbolAddress((void**)&pqr, g_pqr);
    cudaGetSymbolAddress((void**)&pqi, g_pqi);
    cudaGetSymbolAddress((void**)&pkr, g_pkr);
    cudaGetSymbolAddress((void**)&pki, g_pki);
    cudaGetSymbolAddress((void**)&pvr, g_pvr);
    cudaGetSymbolAddress((void**)&pvi, g_pvi);
    cudaGetSymbolAddress((void**)&ar,  g_ar);
    cudaGetSymbolAddress((void**)&ai,  g_ai);
    __nv_bfloat16* ws[16];
    for (int i = 0; i < 16; i++) ws[i] = wsp + (size_t)i * HH * HH;

    // prep
    rowquant_bf16_kernel<<<TT, 256>>>(hr, nr, is1);
    rowquant_bf16_kernel<<<TT, 256>>>(hi, ni, is2);
    cossin_kernel<<<(TT * HD) / 256, 256>>>(pos);
    for (int w = 0; w < 8; w++)
        split_kernel<<<(HH * HH) / 1024, 256>>>(W[w], ws[2 * w], ws[2 * w + 1]);

    // tensor-core (HMMA) dual GEMMs
    const int GSM = STAGES * STG_SZ;  // 131072 bytes
    cudaFuncSetAttribute(gemm_dual_mma, cudaFuncAttributeMaxDynamicSharedMemorySize, GSM);
    dim3 gg(HH / 128, TT / 128);
    // yr = qr@Wr^T + qi@Wi^T ; yi = qr@Wi^T - qi@Wr^T
    gemm_dual_mma<<<gg, 256, GSM>>>(nr, ni, ws[0], ws[1], ws[2], ws[3], is1, is2,  1.f, pqr);
    gemm_dual_mma<<<gg, 256, GSM>>>(nr, ni, ws[2], ws[3], ws[0], ws[1], is1, is2, -1.f, pqi);
    gemm_dual_mma<<<gg, 256, GSM>>>(nr, ni, ws[4], ws[5], ws[6], ws[7], is1, is2,  1.f, pkr);
    gemm_dual_mma<<<gg, 256, GSM>>>(nr, ni, ws[6], ws[7], ws[4], ws[5], is1, is2, -1.f, pki);
    gemm_dual_mma<<<gg, 256, GSM>>>(nr, ni, ws[8], ws[9], ws[10], ws[11], is1, is2,  1.f, pvr);
    gemm_dual_mma<<<gg, 256, GSM>>>(nr, ni, ws[10], ws[11], ws[8], ws[9], is1, is2, -1.f, pvi);

    rope_kernel<<<(TT * HH) / 256, 256>>>(pqr, pqi);
    rope_kernel<<<(TT * HH) / 256, 256>>>(pkr, pki);

    const int FLASH_SMEM = (D2 * QPAD * 2 + 64 * D2 + 64 * PSLD) * 4;
    cudaFuncSetAttribute(flash_kernel, cudaFuncAttributeMaxDynamicSharedMemorySize, FLASH_SMEM);
    flash_kernel<<<dim3(TT / 64, NHEAD), 256, FLASH_SMEM>>>(pqr, pqi, pkr, pki, pvr, pvi, ar, ai);

    // output projection
    rowquant_bf16_kernel<<<TT, 256>>>(ar, nr, is3);
    rowquant_bf16_kernel<<<TT, 256>>>(ai, ni, is4);
    gemm_dual_mma<<<gg, 256, GSM>>>(nr, ni, ws[12], ws[13], ws[14], ws[15], is3, is4,  1.f, out);
    gemm_dual_mma<<<gg, 256, GSM>>>(nr, ni, ws[14], ws[15], ws[12], ws[13], is3, is4, -1.f, out + (size_t)TT * HH);
}

// round 4
// speedup vs baseline: 3.8082x; 1.6864x over previous
#include <cuda_runtime.h>
#include <cuda_bf16.h>
#include <math_constants.h>
#include <cstdint>

#define TT 2048
#define HH 2048
#define NHEAD 16
#define HD 128
#define D2 256

// ======================= scratch (static device globals) =======================
__device__ __nv_bfloat16 g_nr[TT*HH];
__device__ __nv_bfloat16 g_ni[TT*HH];
__device__ float g_invs1[TT];
__device__ float g_invs2[TT];
__device__ float g_invs3[TT];
__device__ float g_invs4[TT];
__device__ __nv_bfloat16 g_wsp[16][HH*HH];
__device__ float g_pqr[TT*HH];
__device__ float g_pqi[TT*HH];
__device__ float g_pkr[TT*HH];
__device__ float g_pki[TT*HH];
__device__ float g_pvr[TT*HH];
__device__ float g_pvi[TT*HH];
__device__ float g_ar[TT*HH];
__device__ float g_ai[TT*HH];
__device__ float g_cos[TT*HD];
__device__ float g_sin[TT*HD];
// per-head hi/lo bf16 arrays for flash: [NH][T][256]
__device__ __nv_bfloat16 g_qhi[NHEAD*TT*D2];
__device__ __nv_bfloat16 g_qlo[NHEAD*TT*D2];
__device__ __nv_bfloat16 g_khi[NHEAD*TT*D2];
__device__ __nv_bfloat16 g_klo[NHEAD*TT*D2];
__device__ __nv_bfloat16 g_vhi[NHEAD*TT*D2];
__device__ __nv_bfloat16 g_vlo[NHEAD*TT*D2];

// ======================= helpers =======================
__device__ __forceinline__ uint32_t smem_u32(const void* p) {
    uint32_t a;
    asm("{ .reg .u64 t; cvta.to.shared.u64 t, %1; cvt.u32.u64 %0, t; }" : "=r"(a) : "l"(p));
    return a;
}
#define SWZ128(b) ((b) ^ (((b) >> 3) & 0x70))
#define SWZ512(b) ((b) ^ (((b) >> 5) & 0x70))

__device__ __forceinline__ uint32_t packbf(float a, float b) {
    __nv_bfloat162 t = __floats2bfloat162_rn(a, b);
    return *(uint32_t*)&t;
}

// ======================= prep kernels =======================
__global__ void rowquant_bf16_kernel(const float* __restrict__ x,
                                     __nv_bfloat16* __restrict__ q,
                                     float* __restrict__ invs) {
    __shared__ float red[256];
    int row = blockIdx.x;
    const float* xr = x + row * HH;
    float m = 0.f;
    for (int c = threadIdx.x; c < HH; c += 256) m = fmaxf(m, fabsf(xr[c]));
    red[threadIdx.x] = m;
    __syncthreads();
    for (int s = 128; s > 0; s >>= 1) {
        if (threadIdx.x < s) red[threadIdx.x] = fmaxf(red[threadIdx.x], red[threadIdx.x + s]);
        __syncthreads();
    }
    float scale = 127.0f / fmaxf(red[0], 1e-5f);
    if (threadIdx.x == 0) invs[row] = 1.0f / scale;
    for (int c = threadIdx.x; c < HH; c += 256) {
        float v = rintf(xr[c] * scale);
        v = fminf(fmaxf(v, -128.f), 127.f);
        q[row * HH + c] = __float2bfloat16_rn(v);
    }
}

__global__ void split_kernel(const float* __restrict__ w,
                             __nv_bfloat16* __restrict__ hi,
                             __nv_bfloat16* __restrict__ lo) {
    int i = (blockIdx.x * 256 + threadIdx.x) * 4;
    float4 v = *(const float4*)(w + i);
    __nv_bfloat16 h[4], l[4];
    float vv[4] = {v.x, v.y, v.z, v.w};
#pragma unroll
    for (int j = 0; j < 4; j++) {
        h[j] = __float2bfloat16_rn(vv[j]);
        l[j] = __float2bfloat16_rn(vv[j] - __bfloat162float(h[j]));
    }
    *(uint64_t*)(hi + i) = *(uint64_t*)h;
    *(uint64_t*)(lo + i) = *(uint64_t*)l;
}

__global__ void cossin_kernel(const int* __restrict__ pos) {
    int idx = blockIdx.x * 256 + threadIdx.x;
    if (idx >= TT * HD) return;
    int t = idx / HD, d = idx % HD;
    float invf = 1.0f / powf(10000.0f, (float)d / (float)HD);
    float f = (float)pos[t] * invf;
    g_cos[idx] = __bfloat162float(__float2bfloat16(cosf(f)));
    g_sin[idx] = __bfloat162float(__float2bfloat16(sinf(f)));
}

// fused (optional rope) + hi/lo bf16 split into per-head layout [NH][T][256]
__global__ void ropesplit_kernel(const float* __restrict__ xr, const float* __restrict__ xi,
                                 __nv_bfloat16* __restrict__ ghi, __nv_bfloat16* __restrict__ glo,
                                 int dorope) {
    int idx = blockIdx.x * 256 + threadIdx.x;   // over T*H
    int t = idx >> 11;
    int colh = idx & 2047;
    int h = colh >> 7, d = colh & 127;
    float r = xr[idx], im = xi[idx];
    if (dorope) {
        float c = g_cos[t * HD + d], s = g_sin[t * HD + d];
        float rr = r * c - im * s;
        float ii = im * c + r * s;
        r = rr; im = ii;
    }
    size_t base = ((size_t)h * TT + t) * D2;
    __nv_bfloat16 rh = __float2bfloat16_rn(r);
    ghi[base + d] = rh;
    glo[base + d] = __float2bfloat16_rn(r - __bfloat162float(rh));
    __nv_bfloat16 ih = __float2bfloat16_rn(im);
    ghi[base + 128 + d] = ih;
    glo[base + 128 + d] = __float2bfloat16_rn(im - __bfloat162float(ih));
}

// ======================= mma.sync dual GEMM (unchanged from R3) =======================
#define STAGES 4
#define NCHUNK 128
#define STG_SZ 32768

__device__ __forceinline__ void load_chunk(uint32_t sa, uint32_t sb,
                                           const __nv_bfloat16* Aseg,
                                           const __nv_bfloat16* Bseg,
                                           int m0, int n0, int kc, int tid) {
    const char* ag = (const char*)(Aseg + (size_t)m0 * HH + kc * 64);
    const char* bg = (const char*)(Bseg + (size_t)n0 * HH + kc * 64);
#pragma unroll
    for (int i = 0; i < 4; i++) {
        int idx = tid + i * 256;
        int r = idx >> 3, g = idx & 7;
        uint32_t so = sa + SWZ128(r * 128 + g * 16);
        asm volatile("cp.async.cg.shared.global [%0], [%1], 16;"
                     :: "r"(so), "l"(ag + (size_t)r * 4096 + g * 16));
    }
#pragma unroll
    for (int i = 0; i < 4; i++) {
        int idx = tid + i * 256;
        int r = idx >> 3, g = idx & 7;
        uint32_t so = sb + SWZ128(r * 128 + g * 16);
        asm volatile("cp.async.cg.shared.global [%0], [%1], 16;"
                     :: "r"(so), "l"(bg + (size_t)r * 4096 + g * 16));
    }
}

__device__ __forceinline__ void compute_chunk(uint32_t sa, uint32_t sb,
                                              int warp_m, int warp_n, int lane,
                                              float (&acc)[4][4][4]) {
#pragma unroll
    for (int ks = 0; ks < 4; ks++) {
        uint32_t af[4][4];
#pragma unroll
        for (int mi = 0; mi < 4; mi++) {
            int r = warp_m * 64 + mi * 16 + (lane & 15);
            int cb = ks * 32 + (lane >> 4) * 16;
            uint32_t ad = sa + SWZ128(r * 128 + cb);
            asm volatile("ldmatrix.sync.aligned.m8n8.x4.shared.b16 {%0,%1,%2,%3}, [%4];"
                : "=r"(af[mi][0]), "=r"(af[mi][1]), "=r"(af[mi][2]), "=r"(af[mi][3])
                : "r"(ad));
        }
        uint32_t bf[4][2];
#pragma unroll
        for (int p = 0; p < 2; p++) {
            int nr = warp_n * 32 + p * 16 + (lane & 7) + ((lane >> 4) << 3);
            int cb = ks * 32 + ((lane >> 3) & 1) * 16;
            uint32_t bd = sb + SWZ128(nr * 128 + cb);
            asm volatile("ldmatrix.sync.aligned.m8n8.x4.shared.b16 {%0,%1,%2,%3}, [%4];"
                : "=r"(bf[2*p][0]), "=r"(bf[2*p][1]), "=r"(bf[2*p+1][0]), "=r"(bf[2*p+1][1])
                : "r"(bd));
        }
#pragma unroll
        for (int mi = 0; mi < 4; mi++)
#pragma unroll
            for (int nj = 0; nj < 4; nj++)
                asm volatile(
                    "mma.sync.aligned.m16n8k16.row.col.f32.bf16.bf16.f32 "
                    "{%0,%1,%2,%3}, {%4,%5,%6,%7}, {%8,%9}, {%0,%1,%2,%3};"
                    : "+f"(acc[mi][nj][0]), "+f"(acc[mi][nj][1]),
                      "+f"(acc[mi][nj][2]), "+f"(acc[mi][nj][3])
                    : "r"(af[mi][0]), "r"(af[mi][1]), "r"(af[mi][2]), "r"(af[mi][3]),
                      "r"(bf[nj][0]), "r"(bf[nj][1]));
    }
}

__global__ __launch_bounds__(256, 1) void gemm_dual_mma(
    const __nv_bfloat16* __restrict__ A1, const __nv_bfloat16* __restrict__ A2,
    const __nv_bfloat16* __restrict__ B1hi, const __nv_bfloat16* __restrict__ B1lo,
    const __nv_bfloat16* __restrict__ B2hi, const __nv_bfloat16* __restrict__ B2lo,
    const float* __restrict__ invs1, const float* __restrict__ invs2,
    float sign, float* __restrict__ C) {
    extern __shared__ char smem[];
    uint32_t sbase = smem_u32(smem);
    int tid = threadIdx.x;
    int wid = tid >> 5, lane = tid & 31;
    int warp_m = wid >> 2, warp_n = wid & 3;
    int m0 = blockIdx.y * 128, n0 = blockIdx.x * 128;

    float acc1[4][4][4], acc2[4][4][4];
#pragma unroll
    for (int a = 0; a < 4; a++)
#pragma unroll
        for (int b = 0; b < 4; b++)
#pragma unroll
            for (int c = 0; c < 4; c++) { acc1[a][b][c] = 0.f; acc2[a][b][c] = 0.f; }

    for (int c = 0; c < STAGES; c++) {
        uint32_t st = sbase + c * STG_SZ;
        load_chunk(st, st + 16384, A1, B1hi, m0, n0, c, tid);
        asm volatile("cp.async.commit_group;");
    }

    for (int c = 0; c < NCHUNK; c++) {
        int stage = c & (STAGES - 1);
        uint32_t st = sbase + stage * STG_SZ;
        int rem = NCHUNK - 1 - c;
        if (rem >= 3)      asm volatile("cp.async.wait_group 3;");
        else if (rem == 2) asm volatile("cp.async.wait_group 2;");
        else if (rem == 1) asm volatile("cp.async.wait_group 1;");
        else               asm volatile("cp.async.wait_group 0;");
        __syncthreads();

        if (c < 64) compute_chunk(st, st + 16384, warp_m, warp_n, lane, acc1);
        else        compute_chunk(st, st + 16384, warp_m, warp_n, lane, acc2);
        __syncthreads();

        int cn = c + STAGES;
        if (cn < NCHUNK) {
            int sel = cn >> 5;
            const __nv_bfloat16* Bseg = (sel == 0) ? B1hi : (sel == 1) ? B1lo
                                       : (sel == 2) ? B2hi : B2lo;
            const __nv_bfloat16* Aseg = (cn >= 64) ? A2 : A1;
            load_chunk(st, st + 16384, Aseg, Bseg, m0, n0, cn & 31, tid);
            asm volatile("cp.async.commit_group;");
        }
    }

    int tq = lane >> 2, tr = lane & 3;
#pragma unroll
    for (int mi = 0; mi < 4; mi++) {
#pragma unroll
        for (int h = 0; h < 2; h++) {
            int row = m0 + warp_m * 64 + mi * 16 + tq + h * 8;
            float a = invs1[row];
            float b = sign * invs2[row];
            float* crow = C + (size_t)row * HH + n0 + warp_n * 32;
#pragma unroll
            for (int nj = 0; nj < 4; nj++) {
                float2 o;
                o.x = a * acc1[mi][nj][2*h]     + b * acc2[mi][nj][2*h];
                o.y = a * acc1[mi][nj][2*h + 1] + b * acc2[mi][nj][2*h + 1];
                *(float2*)(crow + nj * 8 + 2 * tr) = o;
            }
        }
    }
}

// ======================= HMMA flash attention =======================
// BM=64 q-rows/CTA, 4 warps (16 rows each), key blocks of 32, d2=256.
// smem: Qhi@0(32K) Qlo@32K | KV buf b @ 65536+b*65536: Khi+0 Klo+16K Vhi+32K Vlo+48K
#define FSMEM 196608

__global__ __launch_bounds__(128, 1) void flash_mma(
    const __nv_bfloat16* __restrict__ qhi, const __nv_bfloat16* __restrict__ qlo,
    const __nv_bfloat16* __restrict__ khi, const __nv_bfloat16* __restrict__ klo,
    const __nv_bfloat16* __restrict__ vhi, const __nv_bfloat16* __restrict__ vlo,
    float* __restrict__ outr, float* __restrict__ outi) {
    extern __shared__ char sm[];
    uint32_t sb = smem_u32(sm);
    int head = blockIdx.y;
    int qi = (int)gridDim.x - 1 - (int)blockIdx.x;   // heavy blocks first
    int tid = threadIdx.x;
    int warp = tid >> 5, lane = tid & 31;
    size_t hbase = (size_t)head * TT * D2;

    // ---- Q tile load (hi+lo), 64 rows x 512B each
    {
        const char* s0 = (const char*)(qhi + hbase + (size_t)qi * 64 * D2);
        const char* s1 = (const char*)(qlo + hbase + (size_t)qi * 64 * D2);
#pragma unroll
        for (int i = 0; i < 32; i++) {
            int idx = tid + i * 128;
            int mat = idx >> 11, r = (idx >> 5) & 63, g = idx & 31;
            const char* src = (mat == 0 ? s0 : s1) + (size_t)r * 512 + g * 16;
            uint32_t dst = sb + mat * 32768 + SWZ512(r * 512 + g * 16);
            asm volatile("cp.async.cg.shared.global [%0], [%1], 16;" :: "r"(dst), "l"(src));
        }
    }

    int nkb = 2 * (qi + 1);
    const char* kvsrc[4] = {(const char*)(khi + hbase), (const char*)(klo + hbase),
                            (const char*)(vhi + hbase), (const char*)(vlo + hbase)};
    auto loadKV = [&](int kb, int buf) {
        uint32_t base = sb + 65536 + buf * 65536;
#pragma unroll
        for (int i = 0; i < 32; i++) {
            int idx = tid + i * 128;
            int mat = idx >> 10, r = (idx >> 5) & 31, g = idx & 31;
            const char* src = kvsrc[mat] + (size_t)(kb * 32 + r) * 512 + g * 16;
            uint32_t dst = base + mat * 16384 + SWZ512(r * 512 + g * 16);
            asm volatile("cp.async.cg.shared.global [%0], [%1], 16;" :: "r"(dst), "l"(src));
        }
    };
    loadKV(0, 0);
    asm volatile("cp.async.commit_group;");

    float oAcc[32][4];
#pragma unroll
    for (int j = 0; j < 32; j++)
#pragma unroll
        for (int c = 0; c < 4; c++) oAcc[j][c] = 0.f;
    float m0 = -CUDART_INF_F, m1 = -CUDART_INF_F, l0 = 0.f, l1 = 0.f;
    int rowg0 = qi * 64 + warp * 16 + (lane >> 2);

    for (int kb = 0; kb < nkb; kb++) {
        if (kb + 1 < nkb) {
            loadKV(kb + 1, (kb + 1) & 1);
            asm volatile("cp.async.commit_group;");
            asm volatile("cp.async.wait_group 1;");
        } else {
            asm volatile("cp.async.wait_group 0;");
        }
        __syncthreads();
        uint32_t kv = sb + 65536 + (kb & 1) * 65536;

        // ---- S = Q K^T, 3 passes (hi*hi, hi*lo, lo*hi)
        float sAcc[4][4];
#pragma unroll
        for (int j = 0; j < 4; j++)
#pragma unroll
            for (int c = 0; c < 4; c++) sAcc[j][c] = 0.f;
#pragma unroll
        for (int pass = 0; pass < 3; pass++) {
            uint32_t qb_ = sb + (pass == 2 ? 32768 : 0);
            uint32_t kb_ = kv + (pass == 1 ? 16384 : 0);
#pragma unroll
            for (int ks = 0; ks < 16; ks++) {
                uint32_t qa[4];
                uint32_t qaddr = qb_ + SWZ512((warp * 16 + (lane & 15)) * 512
                                              + ks * 32 + (lane >> 4) * 16);
                asm volatile("ldmatrix.sync.aligned.m8n8.x4.shared.b16 {%0,%1,%2,%3}, [%4];"
                    : "=r"(qa[0]), "=r"(qa[1]), "=r"(qa[2]), "=r"(qa[3]) : "r"(qaddr));
                uint32_t bfr[4][2];
#pragma unroll
                for (int p = 0; p < 2; p++) {
                    int nr = p * 16 + (lane & 7) + ((lane >> 4) << 3);
                    uint32_t kaddr = kb_ + SWZ512(nr * 512 + ks * 32 + ((lane >> 3) & 1) * 16);
                    asm volatile("ldmatrix.sync.aligned.m8n8.x4.shared.b16 {%0,%1,%2,%3}, [%4];"
                        : "=r"(bfr[2*p][0]), "=r"(bfr[2*p][1]),
                          "=r"(bfr[2*p+1][0]), "=r"(bfr[2*p+1][1]) : "r"(kaddr));
                }
#pragma unroll
                for (int nj = 0; nj < 4; nj++)
                    asm volatile(
                        "mma.sync.aligned.m16n8k16.row.col.f32.bf16.bf16.f32 "
                        "{%0,%1,%2,%3}, {%4,%5,%6,%7}, {%8,%9}, {%0,%1,%2,%3};"
                        : "+f"(sAcc[nj][0]), "+f"(sAcc[nj][1]),
                          "+f"(sAcc[nj][2]), "+f"(sAcc[nj][3])
                        : "r"(qa[0]), "r"(qa[1]), "r"(qa[2]), "r"(qa[3]),
                          "r"(bfr[nj][0]), "r"(bfr[nj][1]));
            }
        }

        // ---- scale + causal mask + online softmax (registers only)
        float mloc0 = -CUDART_INF_F, mloc1 = -CUDART_INF_F;
#pragma unroll
        for (int nj = 0; nj < 4; nj++)
#pragma unroll
            for (int c = 0; c < 4; c++) {
                float sv = sAcc[nj][c] * 0.0625f;
                int col = kb * 32 + nj * 8 + (lane & 3) * 2 + (c & 1);
                int rg = rowg0 + ((c >> 1) << 3);
                if (col > rg) sv = -1e9f;
                sAcc[nj][c] = sv;
                if (c < 2) mloc0 = fmaxf(mloc0, sv);
                else       mloc1 = fmaxf(mloc1, sv);
            }
        mloc0 = fmaxf(mloc0, __shfl_xor_sync(0xffffffffu, mloc0, 1));
        mloc0 = fmaxf(mloc0, __shfl_xor_sync(0xffffffffu, mloc0, 2));
        mloc1 = fmaxf(mloc1, __shfl_xor_sync(0xffffffffu, mloc1, 1));
        mloc1 = fmaxf(mloc1, __shfl_xor_sync(0xffffffffu, mloc1, 2));
        float mn0 = fmaxf(m0, mloc0), mn1 = fmaxf(m1, mloc1);
        float f0 = __expf(m0 - mn0), f1 = __expf(m1 - mn1);
        m0 = mn0; m1 = mn1;
        float rs0 = 0.f, rs1 = 0.f;
#pragma unroll
        for (int nj = 0; nj < 4; nj++)
#pragma unroll
            for (int c = 0; c < 4; c++) {
                float p = __expf(sAcc[nj][c] - (c < 2 ? mn0 : mn1));
                sAcc[nj][c] = p;
                if (c < 2) rs0 += p; else rs1 += p;
            }
        rs0 += __shfl_xor_sync(0xffffffffu, rs0, 1);
        rs0 += __shfl_xor_sync(0xffffffffu, rs0, 2);
        rs1 += __shfl_xor_sync(0xffffffffu, rs1, 1);
        rs1 += __shfl_xor_sync(0xffffffffu, rs1, 2);
        l0 = l0 * f0 + rs0;
        l1 = l1 * f1 + rs1;
#pragma unroll
        for (int j = 0; j < 32; j++) {
            oAcc[j][0] *= f0; oAcc[j][1] *= f0;
            oAcc[j][2] *= f1; oAcc[j][3] *= f1;
        }

        // ---- pack P hi/lo (S-acc frag layout == A-operand frag layout)
        uint32_t phi[2][4], plo[2][4];
#pragma unroll
        for (int ks2 = 0; ks2 < 2; ks2++) {
            int nb = ks2 * 2;
#pragma unroll
            for (int q = 0; q < 2; q++) {      // q=0 -> rows r0 (c0,c1); q=1 -> rows r1 (c2,c3)
                float a0 = sAcc[nb][2*q], a1 = sAcc[nb][2*q+1];
                float b0 = sAcc[nb+1][2*q], b1 = sAcc[nb+1][2*q+1];
                phi[ks2][q]     = packbf(a0, a1);
                phi[ks2][q + 2] = packbf(b0, b1);
                float a0h = __bfloat162float(__float2bfloat16_rn(a0));
                float a1h = __bfloat162float(__float2bfloat16_rn(a1));
                float b0h = __bfloat162float(__float2bfloat16_rn(b0));
                float b1h = __bfloat162float(__float2bfloat16_rn(b1));
                plo[ks2][q]     = packbf(a0 - a0h, a1 - a1h);
                plo[ks2][q + 2] = packbf(b0 - b0h, b1 - b1h);
            }
        }

        // ---- O += P V, 3 passes (Phi*Vhi, Plo*Vhi, Phi*Vlo)
        uint32_t vbh = kv + 32768, vbl = kv + 49152;
#pragma unroll
        for (int ks2 = 0; ks2 < 2; ks2++) {
#pragma unroll
            for (int nj = 0; nj < 32; nj++) {
                uint32_t off = SWZ512((ks2 * 16 + (lane & 15)) * 512 + nj * 16);
                uint32_t vh0, vh1, vl0, vl1;
                asm volatile("ldmatrix.sync.aligned.m8n8.x2.trans.shared.b16 {%0,%1}, [%2];"
                    : "=r"(vh0), "=r"(vh1) : "r"(vbh + off));
                asm volatile("ldmatrix.sync.aligned.m8n8.x2.trans.shared.b16 {%0,%1}, [%2];"
                    : "=r"(vl0), "=r"(vl1) : "r"(vbl + off));
                asm volatile(
                    "mma.sync.aligned.m16n8k16.row.col.f32.bf16.bf16.f32 "
                    "{%0,%1,%2,%3}, {%4,%5,%6,%7}, {%8,%9}, {%0,%1,%2,%3};"
                    : "+f"(oAcc[nj][0]), "+f"(oAcc[nj][1]), "+f"(oAcc[nj][2]), "+f"(oAcc[nj][3])
                    : "r"(phi[ks2][0]), "r"(phi[ks2][1]), "r"(phi[ks2][2]), "r"(phi[ks2][3]),
                      "r"(vh0), "r"(vh1));
                asm volatile(
                    "mma.sync.aligned.m16n8k16.row.col.f32.bf16.bf16.f32 "
                    "{%0,%1,%2,%3}, {%4,%5,%6,%7}, {%8,%9}, {%0,%1,%2,%3};"
                    : "+f"(oAcc[nj][0]), "+f"(oAcc[nj][1]), "+f"(oAcc[nj][2]), "+f"(oAcc[nj][3])
                    : "r"(plo[ks2][0]), "r"(plo[ks2][1]), "r"(plo[ks2][2]), "r"(plo[ks2][3]),
                      "r"(vh0), "r"(vh1));
                asm volatile(
                    "mma.sync.aligned.m16n8k16.row.col.f32.bf16.bf16.f32 "
                    "{%0,%1,%2,%3}, {%4,%5,%6,%7}, {%8,%9}, {%0,%1,%2,%3};"
                    : "+f"(oAcc[nj][0]), "+f"(oAcc[nj][1]), "+f"(oAcc[nj][2]), "+f"(oAcc[nj][3])
                    : "r"(phi[ks2][0]), "r"(phi[ks2][1]), "r"(phi[ks2][2]), "r"(phi[ks2][3]),
                      "r"(vl0), "r"(vl1));
            }
        }
        __syncthreads();   // compute(kb) done before buffer kb&1 reloaded next iter
    }

    // ---- epilogue: normalize, scatter real/imag halves
    float il0 = 1.0f / l0, il1 = 1.0f / l1;
    int hoff = head * HD;
    int r0 = qi * 64 + warp * 16 + (lane >> 2);
#pragma unroll
    for (int nj = 0; nj < 32; nj++) {
        int col = nj * 8 + (lane & 3) * 2;
        float2 a = make_float2(oAcc[nj][0] * il0, oAcc[nj][1] * il0);
        float2 b = make_float2(oAcc[nj][2] * il1, oAcc[nj][3] * il1);
        if (col < 128) {
            *(float2*)(outr + (size_t)r0 * HH + hoff + col) = a;
            *(float2*)(outr + (size_t)(r0 + 8) * HH + hoff + col) = b;
        } else {
            *(float2*)(outi + (size_t)r0 * HH + hoff + col - 128) = a;
            *(float2*)(outi + (size_t)(r0 + 8) * HH + hoff + col - 128) = b;
        }
    }
}

// ======================= launch =======================
extern "C" void kernel_launch(void* const* d_in, const int* in_sizes, int n_in,
                              void* d_out, int out_size) {
    const float* hr   = (const float*)d_in[0];
    const float* hi   = (const float*)d_in[1];
    const int*   pos  = (const int*)d_in[2];
    const float* W[8] = {(const float*)d_in[3], (const float*)d_in[4],
                         (const float*)d_in[5], (const float*)d_in[6],
                         (const float*)d_in[7], (const float*)d_in[8],
                         (const float*)d_in[9], (const float*)d_in[10]};
    float* out = (float*)d_out;

    __nv_bfloat16 *nr, *ni, *wsp, *qhi, *qlo, *khi, *klo, *vhi, *vlo;
    float *is1, *is2, *is3, *is4, *pqr, *pqi, *pkr, *pki, *pvr, *pvi, *ar, *ai;
    cudaGetSymbolAddress((void**)&nr,  g_nr);
    cudaGetSymbolAddress((void**)&ni,  g_ni);
    cudaGetSymbolAddress((void**)&is1, g_invs1);
    cudaGetSymbolAddress((void**)&is2, g_invs2);
    cudaGetSymbolAddress((void**)&is3, g_invs3);
    cudaGetSymbolAddress((void**)&is4, g_invs4);
    cudaGetSymbolAddress((void**)&wsp, g_wsp);
    cudaGetSymbolAddress((void**)&pqr, g_pqr);
    cudaGetSymbolAddress((void**)&pqi, g_pqi);
    cudaGetSymbolAddress((void**)&pkr, g_pkr);
    cudaGetSymbolAddress((void**)&pki, g_pki);
    cudaGetSymbolAddress((void**)&pvr, g_pvr);
    cudaGetSymbolAddress((void**)&pvi, g_pvi);
    cudaGetSymbolAddress((void**)&ar,  g_ar);
    cudaGetSymbolAddress((void**)&ai,  g_ai);
    cudaGetSymbolAddress((void**)&qhi, g_qhi);
    cudaGetSymbolAddress((void**)&qlo, g_qlo);
    cudaGetSymbolAddress((void**)&khi, g_khi);
    cudaGetSymbolAddress((void**)&klo, g_klo);
    cudaGetSymbolAddress((void**)&vhi, g_vhi);
    cudaGetSymbolAddress((void**)&vlo, g_vlo);
    __nv_bfloat16* ws[16];
    for (int i = 0; i < 16; i++) ws[i] = wsp + (size_t)i * HH * HH;

    // prep
    rowquant_bf16_kernel<<<TT, 256>>>(hr, nr, is1);
    rowquant_bf16_kernel<<<TT, 256>>>(hi, ni, is2);
    cossin_kernel<<<(TT * HD) / 256, 256>>>(pos);
    for (int w = 0; w < 8; w++)
        split_kernel<<<(HH * HH) / 1024, 256>>>(W[w], ws[2 * w], ws[2 * w + 1]);

    // projections (HMMA dual GEMMs)
    const int GSM = STAGES * STG_SZ;
    cudaFuncSetAttribute(gemm_dual_mma, cudaFuncAttributeMaxDynamicSharedMemorySize, GSM);
    dim3 gg(HH / 128, TT / 128);
    gemm_dual_mma<<<gg, 256, GSM>>>(nr, ni, ws[0], ws[1], ws[2], ws[3], is1, is2,  1.f, pqr);
    gemm_dual_mma<<<gg, 256, GSM>>>(nr, ni, ws[2], ws[3], ws[0], ws[1], is1, is2, -1.f, pqi);
    gemm_dual_mma<<<gg, 256, GSM>>>(nr, ni, ws[4], ws[5], ws[6], ws[7], is1, is2,  1.f, pkr);
    gemm_dual_mma<<<gg, 256, GSM>>>(nr, ni, ws[6], ws[7], ws[4], ws[5], is1, is2, -1.f, pki);
    gemm_dual_mma<<<gg, 256, GSM>>>(nr, ni, ws[8], ws[9], ws[10], ws[11], is1, is2,  1.f, pvr);
    gemm_dual_mma<<<gg, 256, GSM>>>(nr, ni, ws[10], ws[11], ws[8], ws[9], is1, is2, -1.f, pvi);

    // rope + hi/lo split into per-head flash layout
    ropesplit_kernel<<<(TT * HH) / 256, 256>>>(pqr, pqi, qhi, qlo, 1);
    ropesplit_kernel<<<(TT * HH) / 256, 256>>>(pkr, pki, khi, klo, 1);
    ropesplit_kernel<<<(TT * HH) / 256, 256>>>(pvr, pvi, vhi, vlo, 0);

    // HMMA flash attention
    cudaFuncSetAttribute(flash_mma, cudaFuncAttributeMaxDynamicSharedMemorySize, FSMEM);
    flash_mma<<<dim3(TT / 64, NHEAD), 128, FSMEM>>>(qhi, qlo, khi, klo, vhi, vlo, ar, ai);

    // output projection
    rowquant_bf16_kernel<<<TT, 256>>>(ar, nr, is3);
    rowquant_bf16_kernel<<<TT, 256>>>(ai, ni, is4);
    gemm_dual_mma<<<gg, 256, GSM>>>(nr, ni, ws[12], ws[13], ws[14], ws[15], is3, is4,  1.f, out);
    gemm_dual_mma<<<gg, 256, GSM>>>(nr, ni, ws[14], ws[15], ws[12], ws[13], is3, is4, -1.f, out + (size_t)TT * HH);
}

// round 5
// speedup vs baseline: 4.2233x; 1.1090x over previous
#include <cuda_runtime.h>
#include <cuda_bf16.h>
#include <math_constants.h>
#include <cstdint>

#define TT 2048
#define HH 2048
#define NHEAD 16
#define HD 128
#define D2 256

// ======================= scratch (static device globals) =======================
__device__ __nv_bfloat16 g_nr[TT*HH];
__device__ __nv_bfloat16 g_ni[TT*HH];
__device__ float g_invs1[TT];
__device__ float g_invs2[TT];
__device__ float g_invs3[TT];
__device__ float g_invs4[TT];
__device__ __nv_bfloat16 g_wsp[16][HH*HH];
__device__ float g_pqr[TT*HH];
__device__ float g_pqi[TT*HH];
__device__ float g_pkr[TT*HH];
__device__ float g_pki[TT*HH];
__device__ float g_pvr[TT*HH];
__device__ float g_pvi[TT*HH];
__device__ float g_ar[TT*HH];
__device__ float g_ai[TT*HH];
__device__ float g_cos[TT*HD];
__device__ float g_sin[TT*HD];
__device__ __nv_bfloat16 g_qhi[NHEAD*TT*D2];
__device__ __nv_bfloat16 g_qlo[NHEAD*TT*D2];
__device__ __nv_bfloat16 g_khi[NHEAD*TT*D2];
__device__ __nv_bfloat16 g_klo[NHEAD*TT*D2];
__device__ __nv_bfloat16 g_vhi[NHEAD*TT*D2];
__device__ __nv_bfloat16 g_vlo[NHEAD*TT*D2];

// ======================= helpers =======================
__device__ __forceinline__ uint32_t smem_u32(const void* p) {
    uint32_t a;
    asm("{ .reg .u64 t; cvta.to.shared.u64 t, %1; cvt.u32.u64 %0, t; }" : "=r"(a) : "l"(p));
    return a;
}
#define SWZ128(b) ((b) ^ (((b) >> 3) & 0x70))
#define SWZ512(b) ((b) ^ (((b) >> 5) & 0x70))

__device__ __forceinline__ uint32_t packbf(float a, float b) {
    __nv_bfloat162 t = __floats2bfloat162_rn(a, b);
    return *(uint32_t*)&t;
}

// ======================= prep kernels =======================
__global__ void rowquant_bf16_kernel(const float* __restrict__ x,
                                     __nv_bfloat16* __restrict__ q,
                                     float* __restrict__ invs) {
    __shared__ float red[256];
    int row = blockIdx.x;
    const float* xr = x + row * HH;
    float m = 0.f;
    for (int c = threadIdx.x; c < HH; c += 256) m = fmaxf(m, fabsf(xr[c]));
    red[threadIdx.x] = m;
    __syncthreads();
    for (int s = 128; s > 0; s >>= 1) {
        if (threadIdx.x < s) red[threadIdx.x] = fmaxf(red[threadIdx.x], red[threadIdx.x + s]);
        __syncthreads();
    }
    float scale = 127.0f / fmaxf(red[0], 1e-5f);
    if (threadIdx.x == 0) invs[row] = 1.0f / scale;
    for (int c = threadIdx.x; c < HH; c += 256) {
        float v = rintf(xr[c] * scale);
        v = fminf(fmaxf(v, -128.f), 127.f);
        q[row * HH + c] = __float2bfloat16_rn(v);
    }
}

__global__ void split_kernel(const float* __restrict__ w,
                             __nv_bfloat16* __restrict__ hi,
                             __nv_bfloat16* __restrict__ lo) {
    int i = (blockIdx.x * 256 + threadIdx.x) * 4;
    float4 v = *(const float4*)(w + i);
    __nv_bfloat16 h[4], l[4];
    float vv[4] = {v.x, v.y, v.z, v.w};
#pragma unroll
    for (int j = 0; j < 4; j++) {
        h[j] = __float2bfloat16_rn(vv[j]);
        l[j] = __float2bfloat16_rn(vv[j] - __bfloat162float(h[j]));
    }
    *(uint64_t*)(hi + i) = *(uint64_t*)h;
    *(uint64_t*)(lo + i) = *(uint64_t*)l;
}

__global__ void cossin_kernel(const int* __restrict__ pos) {
    int idx = blockIdx.x * 256 + threadIdx.x;
    if (idx >= TT * HD) return;
    int t = idx / HD, d = idx % HD;
    float invf = 1.0f / powf(10000.0f, (float)d / (float)HD);
    float f = (float)pos[t] * invf;
    g_cos[idx] = __bfloat162float(__float2bfloat16(cosf(f)));
    g_sin[idx] = __bfloat162float(__float2bfloat16(sinf(f)));
}

__global__ void ropesplit_kernel(const float* __restrict__ xr, const float* __restrict__ xi,
                                 __nv_bfloat16* __restrict__ ghi, __nv_bfloat16* __restrict__ glo,
                                 int dorope) {
    int idx = blockIdx.x * 256 + threadIdx.x;
    int t = idx >> 11;
    int colh = idx & 2047;
    int h = colh >> 7, d = colh & 127;
    float r = xr[idx], im = xi[idx];
    if (dorope) {
        float c = g_cos[t * HD + d], s = g_sin[t * HD + d];
        float rr = r * c - im * s;
        float ii = im * c + r * s;
        r = rr; im = ii;
    }
    size_t base = ((size_t)h * TT + t) * D2;
    __nv_bfloat16 rh = __float2bfloat16_rn(r);
    ghi[base + d] = rh;
    glo[base + d] = __float2bfloat16_rn(r - __bfloat162float(rh));
    __nv_bfloat16 ih = __float2bfloat16_rn(im);
    ghi[base + 128 + d] = ih;
    glo[base + 128 + d] = __float2bfloat16_rn(im - __bfloat162float(ih));
}

// ======================= mma.sync dual GEMM (single-acc, 128x256 tile) =======================
// C[m0:128, n0:256] = invs1[m]*(A1 @ (B1hi+B1lo)^T) + sign*invs2[m]*(A2 @ (B2hi+B2lo)^T)
// Trick: one fp32 accumulator set; rescale by sign*invs1/invs2 at the half-way point,
// scale by sign*invs2 in the epilogue. 8 warps, warp tile 64x64. 4-stage cp.async ring.
#define STAGES 4
#define NCHUNK 128          // 4 passes x 32 k-chunks of 64
#define STG_A  16384        // 128 rows x 128B
#define STG_SZ 49152        // A 16KB + B 32KB
#define GSM    (STAGES * STG_SZ)   // 196608

__device__ __forceinline__ void load_chunk(uint32_t st,
                                           const __nv_bfloat16* Aseg,
                                           const __nv_bfloat16* Bseg,
                                           int m0, int n0, int kc, int tid) {
    const char* ag = (const char*)(Aseg + (size_t)m0 * HH + kc * 64);
    const char* bg = (const char*)(Bseg + (size_t)n0 * HH + kc * 64);
    uint32_t sa = st, sb = st + STG_A;
#pragma unroll
    for (int i = 0; i < 4; i++) {   // A: 128 rows x 8 x 16B
        int idx = tid + i * 256;
        int r = idx >> 3, g = idx & 7;
        uint32_t so = sa + SWZ128(r * 128 + g * 16);
        asm volatile("cp.async.cg.shared.global [%0], [%1], 16;"
                     :: "r"(so), "l"(ag + (size_t)r * 4096 + g * 16));
    }
#pragma unroll
    for (int i = 0; i < 8; i++) {   // B: 256 rows x 8 x 16B
        int idx = tid + i * 256;
        int r = idx >> 3, g = idx & 7;
        uint32_t so = sb + SWZ128(r * 128 + g * 16);
        asm volatile("cp.async.cg.shared.global [%0], [%1], 16;"
                     :: "r"(so), "l"(bg + (size_t)r * 4096 + g * 16));
    }
}

// one K=64 chunk: warp tile 64x64 -> 4 ks x (4 A-ldm + 4 B-ldm + 32 MMA)
__device__ __forceinline__ void compute_chunk(uint32_t st,
                                              int warp_m, int warp_n, int lane,
                                              float (&acc)[4][8][4]) {
    uint32_t sa = st, sb = st + STG_A;
#pragma unroll
    for (int ks = 0; ks < 4; ks++) {
        uint32_t af[4][4];
#pragma unroll
        for (int mi = 0; mi < 4; mi++) {
            int r = warp_m * 64 + mi * 16 + (lane & 15);
            int cb = ks * 32 + (lane >> 4) * 16;
            uint32_t ad = sa + SWZ128(r * 128 + cb);
            asm volatile("ldmatrix.sync.aligned.m8n8.x4.shared.b16 {%0,%1,%2,%3}, [%4];"
                : "=r"(af[mi][0]), "=r"(af[mi][1]), "=r"(af[mi][2]), "=r"(af[mi][3])
                : "r"(ad));
        }
        uint32_t bf[8][2];
#pragma unroll
        for (int p = 0; p < 4; p++) {
            int nr = warp_n * 64 + p * 16 + (lane & 7) + ((lane >> 4) << 3);
            int cb = ks * 32 + ((lane >> 3) & 1) * 16;
            uint32_t bd = sb + SWZ128(nr * 128 + cb);
            asm volatile("ldmatrix.sync.aligned.m8n8.x4.shared.b16 {%0,%1,%2,%3}, [%4];"
                : "=r"(bf[2*p][0]), "=r"(bf[2*p][1]), "=r"(bf[2*p+1][0]), "=r"(bf[2*p+1][1])
                : "r"(bd));
        }
#pragma unroll
        for (int mi = 0; mi < 4; mi++)
#pragma unroll
            for (int nj = 0; nj < 8; nj++)
                asm volatile(
                    "mma.sync.aligned.m16n8k16.row.col.f32.bf16.bf16.f32 "
                    "{%0,%1,%2,%3}, {%4,%5,%6,%7}, {%8,%9}, {%0,%1,%2,%3};"
                    : "+f"(acc[mi][nj][0]), "+f"(acc[mi][nj][1]),
                      "+f"(acc[mi][nj][2]), "+f"(acc[mi][nj][3])
                    : "r"(af[mi][0]), "r"(af[mi][1]), "r"(af[mi][2]), "r"(af[mi][3]),
                      "r"(bf[nj][0]), "r"(bf[nj][1]));
    }
}

__global__ __launch_bounds__(256, 1) void gemm_dual_mma(
    const __nv_bfloat16* __restrict__ A1, const __nv_bfloat16* __restrict__ A2,
    const __nv_bfloat16* __restrict__ B1hi, const __nv_bfloat16* __restrict__ B1lo,
    const __nv_bfloat16* __restrict__ B2hi, const __nv_bfloat16* __restrict__ B2lo,
    const float* __restrict__ invs1, const float* __restrict__ invs2,
    float sign, float* __restrict__ C) {
    extern __shared__ char smem[];
    uint32_t sbase = smem_u32(smem);
    int tid = threadIdx.x;
    int wid = tid >> 5, lane = tid & 31;
    int warp_m = wid >> 2, warp_n = wid & 3;
    int m0 = blockIdx.y * 128, n0 = blockIdx.x * 256;
    int tq = lane >> 2, tr = lane & 3;

    float acc[4][8][4];
#pragma unroll
    for (int a = 0; a < 4; a++)
#pragma unroll
        for (int b = 0; b < 8; b++)
#pragma unroll
            for (int c = 0; c < 4; c++) acc[a][b][c] = 0.f;

    for (int c = 0; c < STAGES; c++) {
        load_chunk(sbase + c * STG_SZ, A1, B1hi, m0, n0, c, tid);
        asm volatile("cp.async.commit_group;");
    }

    for (int c = 0; c < NCHUNK; c++) {
        int stage = c & (STAGES - 1);
        uint32_t st = sbase + stage * STG_SZ;
        int rem = NCHUNK - 1 - c;
        if (rem >= 3)      asm volatile("cp.async.wait_group 3;");
        else if (rem == 2) asm volatile("cp.async.wait_group 2;");
        else if (rem == 1) asm volatile("cp.async.wait_group 1;");
        else               asm volatile("cp.async.wait_group 0;");
        __syncthreads();

        compute_chunk(st, warp_m, warp_n, lane, acc);

        if (c == 63) {
            // acc holds A1@(B1hi+B1lo); rescale so epilogue scale is sign*invs2[row]
#pragma unroll
            for (int mi = 0; mi < 4; mi++)
#pragma unroll
                for (int h = 0; h < 2; h++) {
                    int row = m0 + warp_m * 64 + mi * 16 + tq + h * 8;
                    float ratio = sign * invs1[row] / invs2[row];
#pragma unroll
                    for (int nj = 0; nj < 8; nj++) {
                        acc[mi][nj][2*h]     *= ratio;
                        acc[mi][nj][2*h + 1] *= ratio;
                    }
                }
        }
        __syncthreads();

        int cn = c + STAGES;
        if (cn < NCHUNK) {
            int sel = cn >> 5;
            const __nv_bfloat16* Bseg = (sel == 0) ? B1hi : (sel == 1) ? B1lo
                                       : (sel == 2) ? B2hi : B2lo;
            const __nv_bfloat16* Aseg = (cn >= 64) ? A2 : A1;
            load_chunk(st, Aseg, Bseg, m0, n0, cn & 31, tid);
            asm volatile("cp.async.commit_group;");
        }
    }

    // epilogue: C = sign*invs2[row] * acc
#pragma unroll
    for (int mi = 0; mi < 4; mi++) {
#pragma unroll
        for (int h = 0; h < 2; h++) {
            int row = m0 + warp_m * 64 + mi * 16 + tq + h * 8;
            float fs = sign * invs2[row];
            float* crow = C + (size_t)row * HH + n0 + warp_n * 64;
#pragma unroll
            for (int nj = 0; nj < 8; nj++) {
                float2 o;
                o.x = fs * acc[mi][nj][2*h];
                o.y = fs * acc[mi][nj][2*h + 1];
                *(float2*)(crow + nj * 8 + 2 * tr) = o;
            }
        }
    }
}

// ======================= HMMA flash attention (unchanged from R4) =======================
#define FSMEM 196608

__global__ __launch_bounds__(128, 1) void flash_mma(
    const __nv_bfloat16* __restrict__ qhi, const __nv_bfloat16* __restrict__ qlo,
    const __nv_bfloat16* __restrict__ khi, const __nv_bfloat16* __restrict__ klo,
    const __nv_bfloat16* __restrict__ vhi, const __nv_bfloat16* __restrict__ vlo,
    float* __restrict__ outr, float* __restrict__ outi) {
    extern __shared__ char sm[];
    uint32_t sb = smem_u32(sm);
    int head = blockIdx.y;
    int qi = (int)gridDim.x - 1 - (int)blockIdx.x;
    int tid = threadIdx.x;
    int warp = tid >> 5, lane = tid & 31;
    size_t hbase = (size_t)head * TT * D2;

    {
        const char* s0 = (const char*)(qhi + hbase + (size_t)qi * 64 * D2);
        const char* s1 = (const char*)(qlo + hbase + (size_t)qi * 64 * D2);
#pragma unroll
        for (int i = 0; i < 32; i++) {
            int idx = tid + i * 128;
            int mat = idx >> 11, r = (idx >> 5) & 63, g = idx & 31;
            const char* src = (mat == 0 ? s0 : s1) + (size_t)r * 512 + g * 16;
            uint32_t dst = sb + mat * 32768 + SWZ512(r * 512 + g * 16);
            asm volatile("cp.async.cg.shared.global [%0], [%1], 16;" :: "r"(dst), "l"(src));
        }
    }

    int nkb = 2 * (qi + 1);
    const char* kvsrc[4] = {(const char*)(khi + hbase), (const char*)(klo + hbase),
                            (const char*)(vhi + hbase), (const char*)(vlo + hbase)};
    auto loadKV = [&](int kb, int buf) {
        uint32_t base = sb + 65536 + buf * 65536;
#pragma unroll
        for (int i = 0; i < 32; i++) {
            int idx = tid + i * 128;
            int mat = idx >> 10, r = (idx >> 5) & 31, g = idx & 31;
            const char* src = kvsrc[mat] + (size_t)(kb * 32 + r) * 512 + g * 16;
            uint32_t dst = base + mat * 16384 + SWZ512(r * 512 + g * 16);
            asm volatile("cp.async.cg.shared.global [%0], [%1], 16;" :: "r"(dst), "l"(src));
        }
    };
    loadKV(0, 0);
    asm volatile("cp.async.commit_group;");

    float oAcc[32][4];
#pragma unroll
    for (int j = 0; j < 32; j++)
#pragma unroll
        for (int c = 0; c < 4; c++) oAcc[j][c] = 0.f;
    float m0 = -CUDART_INF_F, m1 = -CUDART_INF_F, l0 = 0.f, l1 = 0.f;
    int rowg0 = qi * 64 + warp * 16 + (lane >> 2);

    for (int kb = 0; kb < nkb; kb++) {
        if (kb + 1 < nkb) {
            loadKV(kb + 1, (kb + 1) & 1);
            asm volatile("cp.async.commit_group;");
            asm volatile("cp.async.wait_group 1;");
        } else {
            asm volatile("cp.async.wait_group 0;");
        }
        __syncthreads();
        uint32_t kv = sb + 65536 + (kb & 1) * 65536;

        float sAcc[4][4];
#pragma unroll
        for (int j = 0; j < 4; j++)
#pragma unroll
            for (int c = 0; c < 4; c++) sAcc[j][c] = 0.f;
#pragma unroll
        for (int pass = 0; pass < 3; pass++) {
            uint32_t qb_ = sb + (pass == 2 ? 32768 : 0);
            uint32_t kb_ = kv + (pass == 1 ? 16384 : 0);
#pragma unroll
            for (int ks = 0; ks < 16; ks++) {
                uint32_t qa[4];
                uint32_t qaddr = qb_ + SWZ512((warp * 16 + (lane & 15)) * 512
                                              + ks * 32 + (lane >> 4) * 16);
                asm volatile("ldmatrix.sync.aligned.m8n8.x4.shared.b16 {%0,%1,%2,%3}, [%4];"
                    : "=r"(qa[0]), "=r"(qa[1]), "=r"(qa[2]), "=r"(qa[3]) : "r"(qaddr));
                uint32_t bfr[4][2];
#pragma unroll
                for (int p = 0; p < 2; p++) {
                    int nr = p * 16 + (lane & 7) + ((lane >> 4) << 3);
                    uint32_t kaddr = kb_ + SWZ512(nr * 512 + ks * 32 + ((lane >> 3) & 1) * 16);
                    asm volatile("ldmatrix.sync.aligned.m8n8.x4.shared.b16 {%0,%1,%2,%3}, [%4];"
                        : "=r"(bfr[2*p][0]), "=r"(bfr[2*p][1]),
                          "=r"(bfr[2*p+1][0]), "=r"(bfr[2*p+1][1]) : "r"(kaddr));
                }
#pragma unroll
                for (int nj = 0; nj < 4; nj++)
                    asm volatile(
                        "mma.sync.aligned.m16n8k16.row.col.f32.bf16.bf16.f32 "
                        "{%0,%1,%2,%3}, {%4,%5,%6,%7}, {%8,%9}, {%0,%1,%2,%3};"
                        : "+f"(sAcc[nj][0]), "+f"(sAcc[nj][1]),
                          "+f"(sAcc[nj][2]), "+f"(sAcc[nj][3])
                        : "r"(qa[0]), "r"(qa[1]), "r"(qa[2]), "r"(qa[3]),
                          "r"(bfr[nj][0]), "r"(bfr[nj][1]));
            }
        }

        float mloc0 = -CUDART_INF_F, mloc1 = -CUDART_INF_F;
#pragma unroll
        for (int nj = 0; nj < 4; nj++)
#pragma unroll
            for (int c = 0; c < 4; c++) {
                float sv = sAcc[nj][c] * 0.0625f;
                int col = kb * 32 + nj * 8 + (lane & 3) * 2 + (c & 1);
                int rg = rowg0 + ((c >> 1) << 3);
                if (col > rg) sv = -1e9f;
                sAcc[nj][c] = sv;
                if (c < 2) mloc0 = fmaxf(mloc0, sv);
                else       mloc1 = fmaxf(mloc1, sv);
            }
        mloc0 = fmaxf(mloc0, __shfl_xor_sync(0xffffffffu, mloc0, 1));
        mloc0 = fmaxf(mloc0, __shfl_xor_sync(0xffffffffu, mloc0, 2));
        mloc1 = fmaxf(mloc1, __shfl_xor_sync(0xffffffffu, mloc1, 1));
        mloc1 = fmaxf(mloc1, __shfl_xor_sync(0xffffffffu, mloc1, 2));
        float mn0 = fmaxf(m0, mloc0), mn1 = fmaxf(m1, mloc1);
        float f0 = __expf(m0 - mn0), f1 = __expf(m1 - mn1);
        m0 = mn0; m1 = mn1;
        float rs0 = 0.f, rs1 = 0.f;
#pragma unroll
        for (int nj = 0; nj < 4; nj++)
#pragma unroll
            for (int c = 0; c < 4; c++) {
                float p = __expf(sAcc[nj][c] - (c < 2 ? mn0 : mn1));
                sAcc[nj][c] = p;
                if (c < 2) rs0 += p; else rs1 += p;
            }
        rs0 += __shfl_xor_sync(0xffffffffu, rs0, 1);
        rs0 += __shfl_xor_sync(0xffffffffu, rs0, 2);
        rs1 += __shfl_xor_sync(0xffffffffu, rs1, 1);
        rs1 += __shfl_xor_sync(0xffffffffu, rs1, 2);
        l0 = l0 * f0 + rs0;
        l1 = l1 * f1 + rs1;
#pragma unroll
        for (int j = 0; j < 32; j++) {
            oAcc[j][0] *= f0; oAcc[j][1] *= f0;
            oAcc[j][2] *= f1; oAcc[j][3] *= f1;
        }

        uint32_t phi[2][4], plo[2][4];
#pragma unroll
        for (int ks2 = 0; ks2 < 2; ks2++) {
            int nb = ks2 * 2;
#pragma unroll
            for (int q = 0; q < 2; q++) {
                float a0 = sAcc[nb][2*q], a1 = sAcc[nb][2*q+1];
                float b0 = sAcc[nb+1][2*q], b1 = sAcc[nb+1][2*q+1];
                phi[ks2][q]     = packbf(a0, a1);
                phi[ks2][q + 2] = packbf(b0, b1);
                float a0h = __bfloat162float(__float2bfloat16_rn(a0));
                float a1h = __bfloat162float(__float2bfloat16_rn(a1));
                float b0h = __bfloat162float(__float2bfloat16_rn(b0));
                float b1h = __bfloat162float(__float2bfloat16_rn(b1));
                plo[ks2][q]     = packbf(a0 - a0h, a1 - a1h);
                plo[ks2][q + 2] = packbf(b0 - b0h, b1 - b1h);
            }
        }

        uint32_t vbh = kv + 32768, vbl = kv + 49152;
#pragma unroll
        for (int ks2 = 0; ks2 < 2; ks2++) {
#pragma unroll
            for (int nj = 0; nj < 32; nj++) {
                uint32_t off = SWZ512((ks2 * 16 + (lane & 15)) * 512 + nj * 16);
                uint32_t vh0, vh1, vl0, vl1;
                asm volatile("ldmatrix.sync.aligned.m8n8.x2.trans.shared.b16 {%0,%1}, [%2];"
                    : "=r"(vh0), "=r"(vh1) : "r"(vbh + off));
                asm volatile("ldmatrix.sync.aligned.m8n8.x2.trans.shared.b16 {%0,%1}, [%2];"
                    : "=r"(vl0), "=r"(vl1) : "r"(vbl + off));
                asm volatile(
                    "mma.sync.aligned.m16n8k16.row.col.f32.bf16.bf16.f32 "
                    "{%0,%1,%2,%3}, {%4,%5,%6,%7}, {%8,%9}, {%0,%1,%2,%3};"
                    : "+f"(oAcc[nj][0]), "+f"(oAcc[nj][1]), "+f"(oAcc[nj][2]), "+f"(oAcc[nj][3])
                    : "r"(phi[ks2][0]), "r"(phi[ks2][1]), "r"(phi[ks2][2]), "r"(phi[ks2][3]),
                      "r"(vh0), "r"(vh1));
                asm volatile(
                    "mma.sync.aligned.m16n8k16.row.col.f32.bf16.bf16.f32 "
                    "{%0,%1,%2,%3}, {%4,%5,%6,%7}, {%8,%9}, {%0,%1,%2,%3};"
                    : "+f"(oAcc[nj][0]), "+f"(oAcc[nj][1]), "+f"(oAcc[nj][2]), "+f"(oAcc[nj][3])
                    : "r"(plo[ks2][0]), "r"(plo[ks2][1]), "r"(plo[ks2][2]), "r"(plo[ks2][3]),
                      "r"(vh0), "r"(vh1));
                asm volatile(
                    "mma.sync.aligned.m16n8k16.row.col.f32.bf16.bf16.f32 "
                    "{%0,%1,%2,%3}, {%4,%5,%6,%7}, {%8,%9}, {%0,%1,%2,%3};"
                    : "+f"(oAcc[nj][0]), "+f"(oAcc[nj][1]), "+f"(oAcc[nj][2]), "+f"(oAcc[nj][3])
                    : "r"(phi[ks2][0]), "r"(phi[ks2][1]), "r"(phi[ks2][2]), "r"(phi[ks2][3]),
                      "r"(vl0), "r"(vl1));
            }
        }
        __syncthreads();
    }

    float il0 = 1.0f / l0, il1 = 1.0f / l1;
    int hoff = head * HD;
    int r0 = qi * 64 + warp * 16 + (lane >> 2);
#pragma unroll
    for (int nj = 0; nj < 32; nj++) {
        int col = nj * 8 + (lane & 3) * 2;
        float2 a = make_float2(oAcc[nj][0] * il0, oAcc[nj][1] * il0);
        float2 b = make_float2(oAcc[nj][2] * il1, oAcc[nj][3] * il1);
        if (col < 128) {
            *(float2*)(outr + (size_t)r0 * HH + hoff + col) = a;
            *(float2*)(outr + (size_t)(r0 + 8) * HH + hoff + col) = b;
        } else {
            *(float2*)(outi + (size_t)r0 * HH + hoff + col - 128) = a;
            *(float2*)(outi + (size_t)(r0 + 8) * HH + hoff + col - 128) = b;
        }
    }
}

// ======================= launch =======================
extern "C" void kernel_launch(void* const* d_in, const int* in_sizes, int n_in,
                              void* d_out, int out_size) {
    const float* hr   = (const float*)d_in[0];
    const float* hi   = (const float*)d_in[1];
    const int*   pos  = (const int*)d_in[2];
    const float* W[8] = {(const float*)d_in[3], (const float*)d_in[4],
                         (const float*)d_in[5], (const float*)d_in[6],
                         (const float*)d_in[7], (const float*)d_in[8],
                         (const float*)d_in[9], (const float*)d_in[10]};
    float* out = (float*)d_out;

    __nv_bfloat16 *nr, *ni, *wsp, *qhi, *qlo, *khi, *klo, *vhi, *vlo;
    float *is1, *is2, *is3, *is4, *pqr, *pqi, *pkr, *pki, *pvr, *pvi, *ar, *ai;
    cudaGetSymbolAddress((void**)&nr,  g_nr);
    cudaGetSymbolAddress((void**)&ni,  g_ni);
    cudaGetSymbolAddress((void**)&is1, g_invs1);
    cudaGetSymbolAddress((void**)&is2, g_invs2);
    cudaGetSymbolAddress((void**)&is3, g_invs3);
    cudaGetSymbolAddress((void**)&is4, g_invs4);
    cudaGetSymbolAddress((void**)&wsp, g_wsp);
    cudaGetSymbolAddress((void**)&pqr, g_pqr);
    cudaGetSymbolAddress((void**)&pqi, g_pqi);
    cudaGetSymbolAddress((void**)&pkr, g_pkr);
    cudaGetSymbolAddress((void**)&pki, g_pki);
    cudaGetSymbolAddress((void**)&pvr, g_pvr);
    cudaGetSymbolAddress((void**)&pvi, g_pvi);
    cudaGetSymbolAddress((void**)&ar,  g_ar);
    cudaGetSymbolAddress((void**)&ai,  g_ai);
    cudaGetSymbolAddress((void**)&qhi, g_qhi);
    cudaGetSymbolAddress((void**)&qlo, g_qlo);
    cudaGetSymbolAddress((void**)&khi, g_khi);
    cudaGetSymbolAddress((void**)&klo, g_klo);
    cudaGetSymbolAddress((void**)&vhi, g_vhi);
    cudaGetSymbolAddress((void**)&vlo, g_vlo);
    __nv_bfloat16* ws[16];
    for (int i = 0; i < 16; i++) ws[i] = wsp + (size_t)i * HH * HH;

    // prep
    rowquant_bf16_kernel<<<TT, 256>>>(hr, nr, is1);
    rowquant_bf16_kernel<<<TT, 256>>>(hi, ni, is2);
    cossin_kernel<<<(TT * HD) / 256, 256>>>(pos);
    for (int w = 0; w < 8; w++)
        split_kernel<<<(HH * HH) / 1024, 256>>>(W[w], ws[2 * w], ws[2 * w + 1]);

    // projections (HMMA dual GEMMs), 128x256 tile -> one wave of 128 CTAs
    cudaFuncSetAttribute(gemm_dual_mma, cudaFuncAttributeMaxDynamicSharedMemorySize, GSM);
    dim3 gg(HH / 256, TT / 128);
    gemm_dual_mma<<<gg, 256, GSM>>>(nr, ni, ws[0], ws[1], ws[2], ws[3], is1, is2,  1.f, pqr);
    gemm_dual_mma<<<gg, 256, GSM>>>(nr, ni, ws[2], ws[3], ws[0], ws[1], is1, is2, -1.f, pqi);
    gemm_dual_mma<<<gg, 256, GSM>>>(nr, ni, ws[4], ws[5], ws[6], ws[7], is1, is2,  1.f, pkr);
    gemm_dual_mma<<<gg, 256, GSM>>>(nr, ni, ws[6], ws[7], ws[4], ws[5], is1, is2, -1.f, pki);
    gemm_dual_mma<<<gg, 256, GSM>>>(nr, ni, ws[8], ws[9], ws[10], ws[11], is1, is2,  1.f, pvr);
    gemm_dual_mma<<<gg, 256, GSM>>>(nr, ni, ws[10], ws[11], ws[8], ws[9], is1, is2, -1.f, pvi);

    // rope + hi/lo split into per-head flash layout
    ropesplit_kernel<<<(TT * HH) / 256, 256>>>(pqr, pqi, qhi, qlo, 1);
    ropesplit_kernel<<<(TT * HH) / 256, 256>>>(pkr, pki, khi, klo, 1);
    ropesplit_kernel<<<(TT * HH) / 256, 256>>>(pvr, pvi, vhi, vlo, 0);

    // HMMA flash attention
    cudaFuncSetAttribute(flash_mma, cudaFuncAttributeMaxDynamicSharedMemorySize, FSMEM);
    flash_mma<<<dim3(TT / 64, NHEAD), 128, FSMEM>>>(qhi, qlo, khi, klo, vhi, vlo, ar, ai);

    // output projection
    rowquant_bf16_kernel<<<TT, 256>>>(ar, nr, is3);
    rowquant_bf16_kernel<<<TT, 256>>>(ai, ni, is4);
    gemm_dual_mma<<<gg, 256, GSM>>>(nr, ni, ws[12], ws[13], ws[14], ws[15], is3, is4,  1.f, out);
    gemm_dual_mma<<<gg, 256, GSM>>>(nr, ni, ws[14], ws[15], ws[12], ws[13], is3, is4, -1.f, out + (size_t)TT * HH);
}